// round 11
// baseline (speedup 1.0000x reference)
#include <cuda_runtime.h>
#include <cuda_fp16.h>
#include <cstdint>

#define NN 100000
#define NE 3200000
#define ET (NE + NN)
#define DIN 512
#define DH 64
#define NBLK 98
#define SPLIT 50176                     // layer split point (multiple of 256)

__device__ __half g_hs1[(size_t)NN * DH];
__device__ __half g_hs2[(size_t)NN * DH];
__device__ float g_a[(size_t)NN * DH];
__device__ float g_bpk[80 * 32 * 20];
__device__ float g_dinv[NN];
__device__ int   g_cnt[NN];
__device__ int   g_rowptr[NN + 1];
__device__ int   g_cursor[NN];
__device__ int   g_col[ET];
__device__ int   g_bsum[128];

__device__ __forceinline__ uint32_t smem_u32(const void* p) {
    uint32_t a;
    asm("{ .reg .u64 t; cvta.to.shared.u64 t, %1; cvt.u32.u64 %0, t; }" : "=r"(a) : "l"(p));
    return a;
}
__device__ __forceinline__ void cpa16(float* dst, const float* src) {
    uint32_t d = smem_u32(dst);
    asm volatile("cp.async.ca.shared.global [%0], [%1], 16;" :: "r"(d), "l"(src) : "memory");
}
__device__ __forceinline__ void cpa_commit() {
    asm volatile("cp.async.commit_group;" ::: "memory");
}
template <int N> __device__ __forceinline__ void cpa_wait() {
    asm volatile("cp.async.wait_group %0;" :: "n"(N) : "memory");
}
__device__ __forceinline__ uint32_t f2tf32(float f) {
    uint32_t u;
    asm("cvt.rna.tf32.f32 %0, %1;" : "=r"(u) : "f"(f));
    return u;
}

__global__ void k_pack(const float* __restrict__ W1, const float* __restrict__ W2,
                       const float* __restrict__ Wlin) {
    int tid = blockIdx.x * blockDim.x + threadIdx.x;
    if (tid >= 80 * 32 * 16) return;
    int s   = tid >> 9;
    int l   = (tid >> 4) & 31;
    int idx = tid & 15;
    int g = l >> 2, tig = l & 3;
    int j = idx & 7;
    int half = idx >> 3;
    const float* W; int sl;
    if (s < 64)      { W = W1;   sl = s; }
    else if (s < 72) { W = W2;   sl = s - 64; }
    else             { W = Wlin; sl = s - 72; }
    int k = sl * 8 + tig + half * 4;
    float v = W[k * DH + 8 * j + g];
    g_bpk[(s * 32 + l) * 20 + idx] = __uint_as_float(f2tf32(v));
}

__global__ void k_init() {
    int i = blockIdx.x * blockDim.x + threadIdx.x;
    if (i < NN) g_cnt[i] = 0;
}

__global__ void k_count(const int* __restrict__ ei) {
    int e = blockIdx.x * blockDim.x + threadIdx.x;
    if (e >= ET) return;
    int d = (e < NE) ? ei[NE + e] : (e - NE);
    atomicAdd(&g_cnt[d], 1);
}

__global__ void k_scan1() {
    __shared__ int s[1024];
    int i = blockIdx.x * 1024 + threadIdx.x;
    int v = (i < NN) ? g_cnt[i] : 0;
    s[threadIdx.x] = v;
    __syncthreads();
    for (int off = 1; off < 1024; off <<= 1) {
        int t = (threadIdx.x >= off) ? s[threadIdx.x - off] : 0;
        __syncthreads();
        s[threadIdx.x] += t;
        __syncthreads();
    }
    if (i < NN) g_rowptr[i] = s[threadIdx.x] - v;
    if (threadIdx.x == 1023) g_bsum[blockIdx.x] = s[1023];
}

__global__ void k_scan2() {
    __shared__ int s[128];
    int t = threadIdx.x;
    int v = (t < NBLK) ? g_bsum[t] : 0;
    s[t] = v;
    __syncthreads();
    for (int off = 1; off < 128; off <<= 1) {
        int u = (t >= off) ? s[t - off] : 0;
        __syncthreads();
        s[t] += u;
        __syncthreads();
    }
    if (t < NBLK) g_bsum[t] = s[t] - v;
}

__global__ void k_scan3() {
    int i = blockIdx.x * blockDim.x + threadIdx.x;
    if (i == 0) g_rowptr[NN] = ET;
    if (i >= NN) return;
    int r = g_rowptr[i] + g_bsum[i >> 10];
    g_rowptr[i] = r;
    g_cursor[i] = r;
    g_dinv[i]   = rsqrtf((float)g_cnt[i]);
}

__global__ void k_fill(const int* __restrict__ ei) {
    int e = blockIdx.x * blockDim.x + threadIdx.x;
    if (e >= ET) return;
    int s, d;
    if (e < NE) { s = ei[e]; d = ei[NE + e]; } else { s = e - NE; d = s; }
    int pos = atomicAdd(&g_cursor[d], 1);
    g_col[pos] = s;
}

// ---------------- GEMM1: g_hs1 = fp16(dinv * (x @ W1)) ----------------
#define AST 36
#define SA_W (256 * AST)
#define SB_W 2560
#define GEMM_SMEM ((2 * SA_W + 2 * SB_W) * 4)   // 94208

__global__ __launch_bounds__(256) void k_gemm1_mma(const float* __restrict__ x) {
    extern __shared__ float sm[];
    float* sA[2] = {sm, sm + SA_W};
    float* sB[2] = {sm + 2 * SA_W, sm + 2 * SA_W + SB_W};
    int t = threadIdx.x;
    int wid = t >> 5, lane = t & 31;
    int g = lane >> 2, tig = lane & 3;
    int row0 = blockIdx.x * 256 + wid * 32;

    float c[2][8][4];
#pragma unroll
    for (int m = 0; m < 2; m++)
#pragma unroll
        for (int j = 0; j < 8; j++)
#pragma unroll
            for (int q = 0; q < 4; q++) c[m][j][q] = 0.f;

    int arow = t >> 3, ajj = t & 7;
    int argl = blockIdx.x * 256 + arow;

    {
#pragma unroll
        for (int p = 0; p < 8; p++) {
            int row = p * 32 + arow;
            int rg = argl + p * 32; if (rg >= NN) rg = NN - 1;
            cpa16(&sA[0][row * AST + ajj * 4], &x[(size_t)rg * DIN + ajj * 4]);
        }
#pragma unroll
        for (int q = 0; q < 3; q++) {
            int i = q * 256 + t;
            if (i < 640) cpa16(&sB[0][i * 4], &g_bpk[i * 4]);
        }
        cpa_commit();
    }

    for (int ch = 0; ch < 16; ch++) {
        int st = ch & 1;
        if (ch < 15) {
            int cn = ch + 1, sn = cn & 1;
#pragma unroll
            for (int p = 0; p < 8; p++) {
                int row = p * 32 + arow;
                int rg = argl + p * 32; if (rg >= NN) rg = NN - 1;
                cpa16(&sA[sn][row * AST + ajj * 4], &x[(size_t)rg * DIN + cn * 32 + ajj * 4]);
            }
#pragma unroll
            for (int q = 0; q < 3; q++) {
                int i = q * 256 + t;
                if (i < 640) cpa16(&sB[sn][i * 4], &g_bpk[cn * SB_W + i * 4]);
            }
            cpa_commit();
            cpa_wait<1>();
        } else {
            cpa_wait<0>();
        }
        __syncthreads();

        const float* A = sA[st];
        const float* B = sB[st];
#pragma unroll
        for (int s = 0; s < 4; s++) {
            uint32_t a[2][4];
#pragma unroll
            for (int m = 0; m < 2; m++) {
                int r0 = wid * 32 + m * 16 + g;
                a[m][0] = f2tf32(A[r0 * AST + s * 8 + tig]);
                a[m][1] = f2tf32(A[(r0 + 8) * AST + s * 8 + tig]);
                a[m][2] = f2tf32(A[r0 * AST + s * 8 + tig + 4]);
                a[m][3] = f2tf32(A[(r0 + 8) * AST + s * 8 + tig + 4]);
            }
            const float4* bp = (const float4*)&B[(s * 32 + lane) * 20];
            float4 q0 = bp[0], q1 = bp[1], q2 = bp[2], q3 = bp[3];
            uint32_t b0[8] = {__float_as_uint(q0.x), __float_as_uint(q0.y),
                              __float_as_uint(q0.z), __float_as_uint(q0.w),
                              __float_as_uint(q1.x), __float_as_uint(q1.y),
                              __float_as_uint(q1.z), __float_as_uint(q1.w)};
            uint32_t b1[8] = {__float_as_uint(q2.x), __float_as_uint(q2.y),
                              __float_as_uint(q2.z), __float_as_uint(q2.w),
                              __float_as_uint(q3.x), __float_as_uint(q3.y),
                              __float_as_uint(q3.z), __float_as_uint(q3.w)};
#pragma unroll
            for (int j = 0; j < 8; j++) {
#pragma unroll
                for (int m = 0; m < 2; m++) {
                    asm volatile(
                        "mma.sync.aligned.m16n8k8.row.col.f32.tf32.tf32.f32 "
                        "{%0,%1,%2,%3}, {%4,%5,%6,%7}, {%8,%9}, {%0,%1,%2,%3};"
                        : "+f"(c[m][j][0]), "+f"(c[m][j][1]),
                          "+f"(c[m][j][2]), "+f"(c[m][j][3])
                        : "r"(a[m][0]), "r"(a[m][1]), "r"(a[m][2]), "r"(a[m][3]),
                          "r"(b0[j]), "r"(b1[j]));
                }
            }
        }
        __syncthreads();
    }

    int R[4];
#pragma unroll
    for (int m = 0; m < 4; m++) {
        int r = row0 + m * 8 + g;
        R[m] = (r < NN) ? r : (NN - 1);
    }
    float di[4];
#pragma unroll
    for (int m = 0; m < 4; m++) di[m] = rsqrtf((float)g_cnt[R[m]]);
#pragma unroll
    for (int m = 0; m < 2; m++) {
        int rA = row0 + m * 16 + g;
        int rB = rA + 8;
#pragma unroll
        for (int j = 0; j < 8; j++) {
            int col = j * 8 + 2 * tig;
            if (rA < NN) {
                __half2 v = __floats2half2_rn(c[m][j][0] * di[2 * m],
                                              c[m][j][1] * di[2 * m]);
                *(__half2*)&g_hs1[(size_t)rA * DH + col] = v;
            }
            if (rB < NN) {
                __half2 v = __floats2half2_rn(c[m][j][2] * di[2 * m + 1],
                                              c[m][j][3] * di[2 * m + 1]);
                *(__half2*)&g_hs1[(size_t)rB * DH + col] = v;
            }
        }
    }
}

// ---------------- gather-sum (round-9 version + node-range base) ---------
template <int MODE>
__global__ __launch_bounds__(256) void k_aggsum(const float* __restrict__ bpre,
                                                int nbase) {
    int t = threadIdx.x;
    int lane = t & 31;
    int node = nbase + blockIdx.x * 8 + (t >> 5);
    if (node >= NN) return;

    const __half* __restrict__ hin = (MODE == 0) ? g_hs1 : g_hs2;
    int js = g_rowptr[node], je = g_rowptr[node + 1];
    float ax = 0.f, ay = 0.f;
    int j = js;
    for (; j + 32 <= je; j += 32) {
        int myc = g_col[j + lane];
#pragma unroll
        for (int l = 0; l < 32; l++) {
            int s = __shfl_sync(0xffffffffu, myc, l);
            float2 v = __half22float2(*(const __half2*)&hin[s * DH + 2 * lane]);
            ax += v.x; ay += v.y;
        }
    }
    if (j < je) {
        int myc = (j + lane < je) ? g_col[j + lane] : 0;
        int m = je - j;
        for (int l = 0; l < m; l++) {
            int s = __shfl_sync(0xffffffffu, myc, l);
            float2 v = __half22float2(*(const __half2*)&hin[s * DH + 2 * lane]);
            ax += v.x; ay += v.y;
        }
    }

    float di = g_dinv[node];
    float2 bp = ((const float2*)bpre)[lane];
    ax = ax * di + bp.x;
    ay = ay * di + bp.y;
    if (MODE == 0) { ax = fmaxf(ax, 0.f); ay = fmaxf(ay, 0.f); }
    float2 o = {ax, ay};
    *(float2*)&g_a[(size_t)node * DH + 2 * lane] = o;
}

// ---------------- mm64 with SMEM-staged A + node-range base --------------
#define FAST 68
#define MM64_SMEM ((256 * FAST + 8 * 32 * 20) * 4)   // 90112

template <int MODE>
__global__ __launch_bounds__(256) void k_mm64(const float* __restrict__ bpost,
                                              float* __restrict__ out, int nbase) {
    extern __shared__ float sm2[];
    float* aS = sm2;
    float* sB = sm2 + 256 * FAST;
    int t = threadIdx.x;
    int wid = t >> 5, lane = t & 31;
    int g = lane >> 2, tig = lane & 3;
    int base = nbase + blockIdx.x * 256;
    int w32 = wid * 32;

    {
        const float4* src = (const float4*)&g_bpk[(64 + MODE * 8) * 640];
        float4* dst = (float4*)sB;
#pragma unroll
        for (int i = 0; i < 5; i++) dst[t + i * 256] = src[t + i * 256];
    }
#pragma unroll
    for (int i = 0; i < 16; i++) {
        int lr = i * 16 + (t >> 4);
        int rg = base + lr; if (rg >= NN) rg = NN - 1;
        float4 v = *(const float4*)&g_a[(size_t)rg * DH + (t & 15) * 4];
        *(float4*)&aS[lr * FAST + (t & 15) * 4] = v;
    }
    __syncthreads();

    float c[2][8][4];
#pragma unroll
    for (int m = 0; m < 2; m++)
#pragma unroll
        for (int j = 0; j < 8; j++)
#pragma unroll
            for (int q = 0; q < 4; q++) c[m][j][q] = 0.f;

#pragma unroll
    for (int s = 0; s < 8; s++) {
        int k0 = s * 8;
        uint32_t a[2][4];
#pragma unroll
        for (int m = 0; m < 2; m++) {
            int r0 = w32 + m * 16 + g;
            a[m][0] = f2tf32(aS[r0 * FAST + k0 + tig]);
            a[m][1] = f2tf32(aS[(r0 + 8) * FAST + k0 + tig]);
            a[m][2] = f2tf32(aS[r0 * FAST + k0 + tig + 4]);
            a[m][3] = f2tf32(aS[(r0 + 8) * FAST + k0 + tig + 4]);
        }
        const float4* bpf = (const float4*)&sB[(s * 32 + lane) * 20];
        float4 q0 = bpf[0], q1 = bpf[1], q2 = bpf[2], q3 = bpf[3];
        uint32_t b0[8] = {__float_as_uint(q0.x), __float_as_uint(q0.y),
                          __float_as_uint(q0.z), __float_as_uint(q0.w),
                          __float_as_uint(q1.x), __float_as_uint(q1.y),
                          __float_as_uint(q1.z), __float_as_uint(q1.w)};
        uint32_t b1[8] = {__float_as_uint(q2.x), __float_as_uint(q2.y),
                          __float_as_uint(q2.z), __float_as_uint(q2.w),
                          __float_as_uint(q3.x), __float_as_uint(q3.y),
                          __float_as_uint(q3.z), __float_as_uint(q3.w)};
#pragma unroll
        for (int j = 0; j < 8; j++) {
#pragma unroll
            for (int m = 0; m < 2; m++) {
                asm volatile(
                    "mma.sync.aligned.m16n8k8.row.col.f32.tf32.tf32.f32 "
                    "{%0,%1,%2,%3}, {%4,%5,%6,%7}, {%8,%9}, {%0,%1,%2,%3};"
                    : "+f"(c[m][j][0]), "+f"(c[m][j][1]),
                      "+f"(c[m][j][2]), "+f"(c[m][j][3])
                    : "r"(a[m][0]), "r"(a[m][1]), "r"(a[m][2]), "r"(a[m][3]),
                      "r"(b0[j]), "r"(b1[j]));
            }
        }
    }

    if (MODE == 0) {
#pragma unroll
        for (int m = 0; m < 2; m++) {
            int rA = base + w32 + m * 16 + g, rB = rA + 8;
            float diA = g_dinv[(rA < NN) ? rA : (NN - 1)];
            float diB = g_dinv[(rB < NN) ? rB : (NN - 1)];
#pragma unroll
            for (int j = 0; j < 8; j++) {
                int col = j * 8 + 2 * tig;
                if (rA < NN) {
                    __half2 v = __floats2half2_rn(c[m][j][0] * diA, c[m][j][1] * diA);
                    *(__half2*)&g_hs2[(size_t)rA * DH + col] = v;
                }
                if (rB < NN) {
                    __half2 v = __floats2half2_rn(c[m][j][2] * diB, c[m][j][3] * diB);
                    *(__half2*)&g_hs2[(size_t)rB * DH + col] = v;
                }
            }
        }
    } else {
#pragma unroll
        for (int m = 0; m < 2; m++) {
            int rA = base + w32 + m * 16 + g, rB = rA + 8;
#pragma unroll
            for (int j = 0; j < 8; j++) {
                int col = j * 8 + 2 * tig;
                float2 bq = *(const float2*)&bpost[col];
                if (rA < NN) {
                    float2 v = {c[m][j][0] + bq.x, c[m][j][1] + bq.y};
                    *(float2*)&out[(size_t)rA * DH + col] = v;
                }
                if (rB < NN) {
                    float2 v = {c[m][j][2] + bq.x, c[m][j][3] + bq.y};
                    *(float2*)&out[(size_t)rB * DH + col] = v;
                }
            }
        }
    }
}

// ---------------- launch: pack||init+count; scans under GEMM; -----------
// ---------------- per-layer aggsum/mm64 software pipeline  ---------------
#define H1_AGG (SPLIT / 8)                       // 6272 blocks
#define H2_AGG ((NN - SPLIT + 7) / 8)            // 6228 blocks
#define H1_MM  (SPLIT / 256)                     // 196 blocks
#define H2_MM  ((NN - SPLIT + 255) / 256)        // 195 blocks

extern "C" void kernel_launch(void* const* d_in, const int* in_sizes, int n_in,
                              void* d_out, int out_size) {
    const float* x    = (const float*)d_in[0];
    const int*   ei   = (const int*)d_in[1];
    const float* W1   = (const float*)d_in[2];
    const float* b1   = (const float*)d_in[3];
    const float* W2   = (const float*)d_in[4];
    const float* b2   = (const float*)d_in[5];
    const float* Wlin = (const float*)d_in[6];
    const float* blin = (const float*)d_in[7];
    float* out = (float*)d_out;

    static cudaStream_t s2 = nullptr;
    static cudaEvent_t e0 = nullptr, ec = nullptr, e2 = nullptr;
    static cudaEvent_t ea1 = nullptr, em1 = nullptr, ea2 = nullptr, em2 = nullptr;
    if (!s2) {   // created on the uncaptured correctness call
        cudaFuncSetAttribute(k_gemm1_mma, cudaFuncAttributeMaxDynamicSharedMemorySize, GEMM_SMEM);
        cudaFuncSetAttribute(k_mm64<0>, cudaFuncAttributeMaxDynamicSharedMemorySize, MM64_SMEM);
        cudaFuncSetAttribute(k_mm64<1>, cudaFuncAttributeMaxDynamicSharedMemorySize, MM64_SMEM);
        cudaStreamCreateWithFlags(&s2, cudaStreamNonBlocking);
        cudaEventCreateWithFlags(&e0, cudaEventDisableTiming);
        cudaEventCreateWithFlags(&ec, cudaEventDisableTiming);
        cudaEventCreateWithFlags(&e2, cudaEventDisableTiming);
        cudaEventCreateWithFlags(&ea1, cudaEventDisableTiming);
        cudaEventCreateWithFlags(&em1, cudaEventDisableTiming);
        cudaEventCreateWithFlags(&ea2, cudaEventDisableTiming);
        cudaEventCreateWithFlags(&em2, cudaEventDisableTiming);
    }

    // fork s2 from capture origin
    cudaEventRecord(e0, 0);
    cudaStreamWaitEvent(s2, e0, 0);

    k_pack <<<160, 256>>>(W1, W2, Wlin);                       // #0 (main)
    k_init <<<(NN + 255) / 256, 256, 0, s2>>>();               // #1 (s2)
    k_count<<<(ET + 255) / 256, 256, 0, s2>>>(ei);             // #2 (s2)
    cudaEventRecord(ec, s2);
    cudaStreamWaitEvent(0, ec, 0);                             // GEMM needs g_cnt
    k_gemm1_mma<<<(NN + 255) / 256, 256, GEMM_SMEM>>>(x);      // #3 (main) <- ncu
    // CSR tail on s2, hidden under GEMM1
    k_scan1<<<NBLK, 1024, 0, s2>>>();                          // #4
    k_scan2<<<1, 128, 0, s2>>>();                              // #5
    k_scan3<<<(NN + 255) / 256, 256, 0, s2>>>();               // #6
    k_fill <<<(ET + 255) / 256, 256, 0, s2>>>(ei);             // #7
    cudaEventRecord(e2, s2);
    cudaStreamWaitEvent(0, e2, 0);                             // join

    // ---- layer 1: aggsum h1 -> {aggsum h2 || mm64 h1} -> mm64 h2 ----
    k_aggsum<0><<<H1_AGG, 256>>>(b1, 0);                       // #8 (main)
    cudaEventRecord(ea1, 0);
    k_aggsum<0><<<H2_AGG, 256>>>(b1, SPLIT);                   // #9 (main)
    cudaStreamWaitEvent(s2, ea1, 0);
    k_mm64<0><<<H1_MM, 256, MM64_SMEM, s2>>>(nullptr, nullptr, 0);      // #10 (s2)
    k_mm64<0><<<H2_MM, 256, MM64_SMEM>>>(nullptr, nullptr, SPLIT);      // #11 (main)
    cudaEventRecord(em1, s2);
    cudaStreamWaitEvent(0, em1, 0);                            // all of g_hs2 ready

    // ---- layer 2: same pipeline ----
    k_aggsum<1><<<H1_AGG, 256>>>(b2, 0);                       // #12 (main)
    cudaEventRecord(ea2, 0);
    k_aggsum<1><<<H2_AGG, 256>>>(b2, SPLIT);                   // #13 (main)
    cudaStreamWaitEvent(s2, ea2, 0);
    k_mm64<1><<<H1_MM, 256, MM64_SMEM, s2>>>(blin, out, 0);    // #14 (s2)
    k_mm64<1><<<H2_MM, 256, MM64_SMEM>>>(blin, out, SPLIT);    // #15 (main)
    cudaEventRecord(em2, s2);
    cudaStreamWaitEvent(0, em2, 0);                            // sink s2 into main
}

// round 14
// speedup vs baseline: 1.0470x; 1.0470x over previous
#include <cuda_runtime.h>
#include <cuda_fp16.h>
#include <cstdint>

#define NN 100000
#define NE 3200000
#define ET (NE + NN)
#define DIN 512
#define DH 64
#define NBLK 98

__device__ __half g_hs1[(size_t)NN * DH];   // fp16: x@W1 (raw, scaled by k_scale1)
__device__ __half g_hs2[(size_t)NN * DH];   // fp16: dinv*(a@W2)
__device__ float g_a[(size_t)NN * DH];
__device__ float g_bpk[80 * 32 * 20];       // 20-stride pack (mm64 LDS path)
__device__ float g_bpkg[64 * 512];          // coalesced pack (GEMM1 LDG path)
__device__ float g_dinv[NN];
__device__ int   g_cnt[NN];
__device__ int   g_rowptr[NN + 1];
__device__ int   g_cursor[NN];
__device__ int   g_col[ET];
__device__ int   g_bsum[128];

__device__ __forceinline__ uint32_t smem_u32(const void* p) {
    uint32_t a;
    asm("{ .reg .u64 t; cvta.to.shared.u64 t, %1; cvt.u32.u64 %0, t; }" : "=r"(a) : "l"(p));
    return a;
}
__device__ __forceinline__ void cpa16(float* dst, const float* src) {
    uint32_t d = smem_u32(dst);
    asm volatile("cp.async.ca.shared.global [%0], [%1], 16;" :: "r"(d), "l"(src) : "memory");
}
__device__ __forceinline__ void cpa_commit() {
    asm volatile("cp.async.commit_group;" ::: "memory");
}
template <int N> __device__ __forceinline__ void cpa_wait() {
    asm volatile("cp.async.wait_group %0;" :: "n"(N) : "memory");
}
__device__ __forceinline__ uint32_t f2tf32(float f) {
    uint32_t u;
    asm("cvt.rna.tf32.f32 %0, %1;" : "=r"(u) : "f"(f));
    return u;
}

__global__ void k_pack(const float* __restrict__ W1, const float* __restrict__ W2,
                       const float* __restrict__ Wlin) {
    int tid = blockIdx.x * blockDim.x + threadIdx.x;
    if (tid >= 80 * 32 * 16) return;
    int s   = tid >> 9;
    int l   = (tid >> 4) & 31;
    int idx = tid & 15;
    int g = l >> 2, tig = l & 3;
    int j = idx & 7;
    int half = idx >> 3;
    const float* W; int sl;
    if (s < 64)      { W = W1;   sl = s; }
    else if (s < 72) { W = W2;   sl = s - 64; }
    else             { W = Wlin; sl = s - 72; }
    int k = sl * 8 + tig + half * 4;
    float v = W[k * DH + 8 * j + g];
    float pv = __uint_as_float(f2tf32(v));
    g_bpk[(s * 32 + l) * 20 + idx] = pv;
    if (s < 64)   // coalesced layout for GEMM1: [kstep][quarter][lane][4]
        g_bpkg[s * 512 + (idx >> 2) * 128 + l * 4 + (idx & 3)] = pv;
}

__global__ void k_init() {
    int i = blockIdx.x * blockDim.x + threadIdx.x;
    if (i < NN) g_cnt[i] = 0;
}

__global__ void k_count(const int* __restrict__ ei) {
    int e = blockIdx.x * blockDim.x + threadIdx.x;
    if (e >= ET) return;
    int d = (e < NE) ? ei[NE + e] : (e - NE);
    atomicAdd(&g_cnt[d], 1);
}

__global__ void k_scan1() {
    __shared__ int s[1024];
    int i = blockIdx.x * 1024 + threadIdx.x;
    int v = (i < NN) ? g_cnt[i] : 0;
    s[threadIdx.x] = v;
    __syncthreads();
    for (int off = 1; off < 1024; off <<= 1) {
        int t = (threadIdx.x >= off) ? s[threadIdx.x - off] : 0;
        __syncthreads();
        s[threadIdx.x] += t;
        __syncthreads();
    }
    if (i < NN) g_rowptr[i] = s[threadIdx.x] - v;
    if (threadIdx.x == 1023) g_bsum[blockIdx.x] = s[1023];
}

__global__ void k_scan2() {
    __shared__ int s[128];
    int t = threadIdx.x;
    int v = (t < NBLK) ? g_bsum[t] : 0;
    s[t] = v;
    __syncthreads();
    for (int off = 1; off < 128; off <<= 1) {
        int u = (t >= off) ? s[t - off] : 0;
        __syncthreads();
        s[t] += u;
        __syncthreads();
    }
    if (t < NBLK) g_bsum[t] = s[t] - v;
}

__global__ void k_scan3() {
    int i = blockIdx.x * blockDim.x + threadIdx.x;
    if (i == 0) g_rowptr[NN] = ET;
    if (i >= NN) return;
    int r = g_rowptr[i] + g_bsum[i >> 10];
    g_rowptr[i] = r;
    g_cursor[i] = r;
    g_dinv[i]   = rsqrtf((float)g_cnt[i]);
}

__global__ void k_fill(const int* __restrict__ ei) {
    int e = blockIdx.x * blockDim.x + threadIdx.x;
    if (e >= ET) return;
    int s, d;
    if (e < NE) { s = ei[e]; d = ei[NE + e]; } else { s = e - NE; d = s; }
    int pos = atomicAdd(&g_cursor[d], 1);
    g_col[pos] = s;
}

// ---------------- GEMM1: g_hs1 = fp16(x @ W1)  (raw; no CSR dependency) --
// Block 128 thr / M=128; A 2-stage cp.async SMEM (36.9KB); B via coalesced
// LDG.128 from g_bpkg (L1-resident). 4 CTAs/SM (register-limited).
#define AST 36
#define SA_W (128 * AST)                       // 4608 floats/stage
#define GEMM_SMEM (2 * SA_W * 4)               // 36864 bytes

__global__ __launch_bounds__(128) void k_gemm1_mma(const float* __restrict__ x) {
    extern __shared__ float sm[];
    float* sA[2] = {sm, sm + SA_W};
    int t = threadIdx.x;
    int wid = t >> 5, lane = t & 31;
    int g = lane >> 2, tig = lane & 3;
    int row0 = blockIdx.x * 128 + wid * 32;

    float c[2][8][4];
#pragma unroll
    for (int m = 0; m < 2; m++)
#pragma unroll
        for (int j = 0; j < 8; j++)
#pragma unroll
            for (int q = 0; q < 4; q++) c[m][j][q] = 0.f;

    int arow = t >> 3, ajj = t & 7;            // 16 rows/pass, 8 passes
    int argl = blockIdx.x * 128 + arow;

    {
#pragma unroll
        for (int p = 0; p < 8; p++) {
            int row = p * 16 + arow;
            int rg = argl + p * 16; if (rg >= NN) rg = NN - 1;
            cpa16(&sA[0][row * AST + ajj * 4], &x[(size_t)rg * DIN + ajj * 4]);
        }
        cpa_commit();
    }

    for (int ch = 0; ch < 16; ch++) {
        int st = ch & 1;
        if (ch < 15) {
            int cn = ch + 1, sn = cn & 1;
#pragma unroll
            for (int p = 0; p < 8; p++) {
                int row = p * 16 + arow;
                int rg = argl + p * 16; if (rg >= NN) rg = NN - 1;
                cpa16(&sA[sn][row * AST + ajj * 4], &x[(size_t)rg * DIN + cn * 32 + ajj * 4]);
            }
            cpa_commit();
            cpa_wait<1>();
        } else {
            cpa_wait<0>();
        }
        __syncthreads();

        const float* A = sA[st];
#pragma unroll
        for (int s = 0; s < 4; s++) {
            uint32_t a[2][4];
#pragma unroll
            for (int m = 0; m < 2; m++) {
                int r0 = wid * 32 + m * 16 + g;
                a[m][0] = f2tf32(A[r0 * AST + s * 8 + tig]);
                a[m][1] = f2tf32(A[(r0 + 8) * AST + s * 8 + tig]);
                a[m][2] = f2tf32(A[r0 * AST + s * 8 + tig + 4]);
                a[m][3] = f2tf32(A[(r0 + 8) * AST + s * 8 + tig + 4]);
            }
            const float* bb = &g_bpkg[(ch * 4 + s) * 512];
            float4 f0 = *(const float4*)&bb[0 * 128 + lane * 4];
            float4 f1 = *(const float4*)&bb[1 * 128 + lane * 4];
            float4 f2 = *(const float4*)&bb[2 * 128 + lane * 4];
            float4 f3 = *(const float4*)&bb[3 * 128 + lane * 4];
            uint32_t b0[8] = {__float_as_uint(f0.x), __float_as_uint(f0.y),
                              __float_as_uint(f0.z), __float_as_uint(f0.w),
                              __float_as_uint(f1.x), __float_as_uint(f1.y),
                              __float_as_uint(f1.z), __float_as_uint(f1.w)};
            uint32_t b1[8] = {__float_as_uint(f2.x), __float_as_uint(f2.y),
                              __float_as_uint(f2.z), __float_as_uint(f2.w),
                              __float_as_uint(f3.x), __float_as_uint(f3.y),
                              __float_as_uint(f3.z), __float_as_uint(f3.w)};
#pragma unroll
            for (int j = 0; j < 8; j++) {
#pragma unroll
                for (int m = 0; m < 2; m++) {
                    asm volatile(
                        "mma.sync.aligned.m16n8k8.row.col.f32.tf32.tf32.f32 "
                        "{%0,%1,%2,%3}, {%4,%5,%6,%7}, {%8,%9}, {%0,%1,%2,%3};"
                        : "+f"(c[m][j][0]), "+f"(c[m][j][1]),
                          "+f"(c[m][j][2]), "+f"(c[m][j][3])
                        : "r"(a[m][0]), "r"(a[m][1]), "r"(a[m][2]), "r"(a[m][3]),
                          "r"(b0[j]), "r"(b1[j]));
                }
            }
        }
        __syncthreads();
    }

    // epilogue: raw fp16 store (no dinv — applied by k_scale1)
#pragma unroll
    for (int m = 0; m < 2; m++) {
        int rA = row0 + m * 16 + g;
        int rB = rA + 8;
#pragma unroll
        for (int j = 0; j < 8; j++) {
            int col = j * 8 + 2 * tig;
            if (rA < NN) {
                __half2 v = __floats2half2_rn(c[m][j][0], c[m][j][1]);
                *(__half2*)&g_hs1[(size_t)rA * DH + col] = v;
            }
            if (rB < NN) {
                __half2 v = __floats2half2_rn(c[m][j][2], c[m][j][3]);
                *(__half2*)&g_hs1[(size_t)rB * DH + col] = v;
            }
        }
    }
}

// ---------------- scale hs1 by dinv (after CSR join) ----------------
__global__ void k_scale1() {
    int i = blockIdx.x * blockDim.x + threadIdx.x;   // one uint4 = 8 halves
    if (i >= NN * DH / 8) return;
    float di = g_dinv[i >> 3];
    __half2* p = (__half2*)&g_hs1[(size_t)i * 8];
#pragma unroll
    for (int q = 0; q < 4; q++) {
        float2 v = __half22float2(p[q]);
        p[q] = __floats2half2_rn(v.x * di, v.y * di);
    }
}

// ---------------- gather-sum (R9 version) ----------------
template <int MODE>
__global__ __launch_bounds__(256) void k_aggsum(const float* __restrict__ bpre) {
    int t = threadIdx.x;
    int lane = t & 31;
    int node = blockIdx.x * 8 + (t >> 5);
    if (node >= NN) return;

    const __half* __restrict__ hin = (MODE == 0) ? g_hs1 : g_hs2;
    int js = g_rowptr[node], je = g_rowptr[node + 1];
    float ax = 0.f, ay = 0.f;
    int j = js;
    for (; j + 32 <= je; j += 32) {
        int myc = g_col[j + lane];
#pragma unroll
        for (int l = 0; l < 32; l++) {
            int s = __shfl_sync(0xffffffffu, myc, l);
            float2 v = __half22float2(*(const __half2*)&hin[s * DH + 2 * lane]);
            ax += v.x; ay += v.y;
        }
    }
    if (j < je) {
        int myc = (j + lane < je) ? g_col[j + lane] : 0;
        int m = je - j;
        for (int l = 0; l < m; l++) {
            int s = __shfl_sync(0xffffffffu, myc, l);
            float2 v = __half22float2(*(const __half2*)&hin[s * DH + 2 * lane]);
            ax += v.x; ay += v.y;
        }
    }

    float di = g_dinv[node];
    float2 bp = ((const float2*)bpre)[lane];
    ax = ax * di + bp.x;
    ay = ay * di + bp.y;
    if (MODE == 0) { ax = fmaxf(ax, 0.f); ay = fmaxf(ay, 0.f); }
    float2 o = {ax, ay};
    *(float2*)&g_a[(size_t)node * DH + 2 * lane] = o;
}

// ---------------- mm64 with SMEM-staged A (R9 version) ----------------
#define FAST 68
#define MM64_SMEM ((256 * FAST + 8 * 32 * 20) * 4)   // 90112

template <int MODE>
__global__ __launch_bounds__(256) void k_mm64(const float* __restrict__ bpost,
                                              float* __restrict__ out) {
    extern __shared__ float sm2[];
    float* aS = sm2;
    float* sB = sm2 + 256 * FAST;
    int t = threadIdx.x;
    int wid = t >> 5, lane = t & 31;
    int g = lane >> 2, tig = lane & 3;
    int base = blockIdx.x * 256;
    int w32 = wid * 32;

    {
        const float4* src = (const float4*)&g_bpk[(64 + MODE * 8) * 640];
        float4* dst = (float4*)sB;
#pragma unroll
        for (int i = 0; i < 5; i++) dst[t + i * 256] = src[t + i * 256];
    }
#pragma unroll
    for (int i = 0; i < 16; i++) {
        int lr = i * 16 + (t >> 4);
        int rg = base + lr; if (rg >= NN) rg = NN - 1;
        float4 v = *(const float4*)&g_a[(size_t)rg * DH + (t & 15) * 4];
        *(float4*)&aS[lr * FAST + (t & 15) * 4] = v;
    }
    __syncthreads();

    float c[2][8][4];
#pragma unroll
    for (int m = 0; m < 2; m++)
#pragma unroll
        for (int j = 0; j < 8; j++)
#pragma unroll
            for (int q = 0; q < 4; q++) c[m][j][q] = 0.f;

#pragma unroll
    for (int s = 0; s < 8; s++) {
        int k0 = s * 8;
        uint32_t a[2][4];
#pragma unroll
        for (int m = 0; m < 2; m++) {
            int r0 = w32 + m * 16 + g;
            a[m][0] = f2tf32(aS[r0 * FAST + k0 + tig]);
            a[m][1] = f2tf32(aS[(r0 + 8) * FAST + k0 + tig]);
            a[m][2] = f2tf32(aS[r0 * FAST + k0 + tig + 4]);
            a[m][3] = f2tf32(aS[(r0 + 8) * FAST + k0 + tig + 4]);
        }
        const float4* bpf = (const float4*)&sB[(s * 32 + lane) * 20];
        float4 q0 = bpf[0], q1 = bpf[1], q2 = bpf[2], q3 = bpf[3];
        uint32_t b0[8] = {__float_as_uint(q0.x), __float_as_uint(q0.y),
                          __float_as_uint(q0.z), __float_as_uint(q0.w),
                          __float_as_uint(q1.x), __float_as_uint(q1.y),
                          __float_as_uint(q1.z), __float_as_uint(q1.w)};
        uint32_t b1[8] = {__float_as_uint(q2.x), __float_as_uint(q2.y),
                          __float_as_uint(q2.z), __float_as_uint(q2.w),
                          __float_as_uint(q3.x), __float_as_uint(q3.y),
                          __float_as_uint(q3.z), __float_as_uint(q3.w)};
#pragma unroll
        for (int j = 0; j < 8; j++) {
#pragma unroll
            for (int m = 0; m < 2; m++) {
                asm volatile(
                    "mma.sync.aligned.m16n8k8.row.col.f32.tf32.tf32.f32 "
                    "{%0,%1,%2,%3}, {%4,%5,%6,%7}, {%8,%9}, {%0,%1,%2,%3};"
                    : "+f"(c[m][j][0]), "+f"(c[m][j][1]),
                      "+f"(c[m][j][2]), "+f"(c[m][j][3])
                    : "r"(a[m][0]), "r"(a[m][1]), "r"(a[m][2]), "r"(a[m][3]),
                      "r"(b0[j]), "r"(b1[j]));
            }
        }
    }

    if (MODE == 0) {
#pragma unroll
        for (int m = 0; m < 2; m++) {
            int rA = base + w32 + m * 16 + g, rB = rA + 8;
            float diA = g_dinv[(rA < NN) ? rA : (NN - 1)];
            float diB = g_dinv[(rB < NN) ? rB : (NN - 1)];
#pragma unroll
            for (int j = 0; j < 8; j++) {
                int col = j * 8 + 2 * tig;
                if (rA < NN) {
                    __half2 v = __floats2half2_rn(c[m][j][0] * diA, c[m][j][1] * diA);
                    *(__half2*)&g_hs2[(size_t)rA * DH + col] = v;
                }
                if (rB < NN) {
                    __half2 v = __floats2half2_rn(c[m][j][2] * diB, c[m][j][3] * diB);
                    *(__half2*)&g_hs2[(size_t)rB * DH + col] = v;
                }
            }
        }
    } else {
#pragma unroll
        for (int m = 0; m < 2; m++) {
            int rA = base + w32 + m * 16 + g, rB = rA + 8;
#pragma unroll
            for (int j = 0; j < 8; j++) {
                int col = j * 8 + 2 * tig;
                float2 bq = *(const float2*)&bpost[col];
                if (rA < NN) {
                    float2 v = {c[m][j][0] + bq.x, c[m][j][1] + bq.y};
                    *(float2*)&out[(size_t)rA * DH + col] = v;
                }
                if (rB < NN) {
                    float2 v = {c[m][j][2] + bq.x, c[m][j][3] + bq.y};
                    *(float2*)&out[(size_t)rB * DH + col] = v;
                }
            }
        }
    }
}

// ---------------- launch ----------------
extern "C" void kernel_launch(void* const* d_in, const int* in_sizes, int n_in,
                              void* d_out, int out_size) {
    const float* x    = (const float*)d_in[0];
    const int*   ei   = (const int*)d_in[1];
    const float* W1   = (const float*)d_in[2];
    const float* b1   = (const float*)d_in[3];
    const float* W2   = (const float*)d_in[4];
    const float* b2   = (const float*)d_in[5];
    const float* Wlin = (const float*)d_in[6];
    const float* blin = (const float*)d_in[7];
    float* out = (float*)d_out;

    static cudaStream_t s2 = nullptr;
    static cudaEvent_t e0 = nullptr, e2 = nullptr;
    if (!s2) {   // created on the uncaptured correctness call
        cudaFuncSetAttribute(k_gemm1_mma, cudaFuncAttributeMaxDynamicSharedMemorySize, GEMM_SMEM);
        cudaFuncSetAttribute(k_mm64<0>, cudaFuncAttributeMaxDynamicSharedMemorySize, MM64_SMEM);
        cudaFuncSetAttribute(k_mm64<1>, cudaFuncAttributeMaxDynamicSharedMemorySize, MM64_SMEM);
        cudaStreamCreateWithFlags(&s2, cudaStreamNonBlocking);
        cudaEventCreateWithFlags(&e0, cudaEventDisableTiming);
        cudaEventCreateWithFlags(&e2, cudaEventDisableTiming);
    }

    // fork s2 from capture origin; GEMM has NO CSR dependency now
    cudaEventRecord(e0, 0);
    cudaStreamWaitEvent(s2, e0, 0);

    k_pack <<<160, 256>>>(W1, W2, Wlin);                       // #0 (main)
    k_init <<<(NN + 255) / 256, 256, 0, s2>>>();               // #1 (s2)
    k_count<<<(ET + 255) / 256, 256, 0, s2>>>(ei);             // #2 (s2)
    k_gemm1_mma<<<(NN + 127) / 128, 128, GEMM_SMEM>>>(x);      // #3 (main) <- ncu
    k_scan1<<<NBLK, 1024, 0, s2>>>();                          // #4 (s2)
    k_scan2<<<1, 128, 0, s2>>>();                              // #5 (s2)
    k_scan3<<<(NN + 255) / 256, 256, 0, s2>>>();               // #6 (s2)
    k_fill <<<(ET + 255) / 256, 256, 0, s2>>>(ei);             // #7 (s2)
    cudaEventRecord(e2, s2);
    cudaStreamWaitEvent(0, e2, 0);                             // join

    k_scale1<<<(NN * DH / 8 + 255) / 256, 256>>>();            // #8
    k_aggsum<0><<<NN / 8 + 1, 256>>>(b1);                      // #9
    k_mm64<0><<<(NN + 255) / 256, 256, MM64_SMEM>>>(nullptr, nullptr);  // #10
    k_aggsum<1><<<NN / 8 + 1, 256>>>(b2);                      // #11
    k_mm64<1><<<(NN + 255) / 256, 256, MM64_SMEM>>>(blin, out);         // #12
}

// round 15
// speedup vs baseline: 1.0574x; 1.0099x over previous
#include <cuda_runtime.h>
#include <cuda_fp16.h>
#include <cstdint>

#define NN 100000
#define NE 3200000
#define ET (NE + NN)
#define DIN 512
#define DH 64
#define NBLK 98

__device__ __half g_hs1[(size_t)NN * DH];   // fp16: x@W1 (raw; scaled by k_scale1)
__device__ __half g_hs2[(size_t)NN * DH];   // fp16: dinv*(a@W2)
__device__ float g_a[(size_t)NN * DH];
__device__ float g_bpk[80 * 32 * 20];
__device__ float g_dinv[NN];
__device__ int   g_cnt[NN];
__device__ int   g_rowptr[NN + 1];
__device__ int   g_cursor[NN];
__device__ int   g_col[ET];
__device__ int   g_bsum[128];

__device__ __forceinline__ uint32_t smem_u32(const void* p) {
    uint32_t a;
    asm("{ .reg .u64 t; cvta.to.shared.u64 t, %1; cvt.u32.u64 %0, t; }" : "=r"(a) : "l"(p));
    return a;
}
__device__ __forceinline__ void cpa16(float* dst, const float* src) {
    uint32_t d = smem_u32(dst);
    asm volatile("cp.async.ca.shared.global [%0], [%1], 16;" :: "r"(d), "l"(src) : "memory");
}
__device__ __forceinline__ void cpa_commit() {
    asm volatile("cp.async.commit_group;" ::: "memory");
}
template <int N> __device__ __forceinline__ void cpa_wait() {
    asm volatile("cp.async.wait_group %0;" :: "n"(N) : "memory");
}
__device__ __forceinline__ uint32_t f2tf32(float f) {
    uint32_t u;
    asm("cvt.rna.tf32.f32 %0, %1;" : "=r"(u) : "f"(f));
    return u;
}

__global__ void k_pack(const float* __restrict__ W1, const float* __restrict__ W2,
                       const float* __restrict__ Wlin) {
    int tid = blockIdx.x * blockDim.x + threadIdx.x;
    if (tid >= 80 * 32 * 16) return;
    int s   = tid >> 9;
    int l   = (tid >> 4) & 31;
    int idx = tid & 15;
    int g = l >> 2, tig = l & 3;
    int j = idx & 7;
    int half = idx >> 3;
    const float* W; int sl;
    if (s < 64)      { W = W1;   sl = s; }
    else if (s < 72) { W = W2;   sl = s - 64; }
    else             { W = Wlin; sl = s - 72; }
    int k = sl * 8 + tig + half * 4;
    float v = W[k * DH + 8 * j + g];
    g_bpk[(s * 32 + l) * 20 + idx] = __uint_as_float(f2tf32(v));
}

__global__ void k_init() {
    int i = blockIdx.x * blockDim.x + threadIdx.x;
    if (i < NN) g_cnt[i] = 0;
}

__global__ void k_count(const int* __restrict__ ei) {
    int e = blockIdx.x * blockDim.x + threadIdx.x;
    if (e >= ET) return;
    int d = (e < NE) ? ei[NE + e] : (e - NE);
    atomicAdd(&g_cnt[d], 1);
}

__global__ void k_scan1() {
    __shared__ int s[1024];
    int i = blockIdx.x * 1024 + threadIdx.x;
    int v = (i < NN) ? g_cnt[i] : 0;
    s[threadIdx.x] = v;
    __syncthreads();
    for (int off = 1; off < 1024; off <<= 1) {
        int t = (threadIdx.x >= off) ? s[threadIdx.x - off] : 0;
        __syncthreads();
        s[threadIdx.x] += t;
        __syncthreads();
    }
    if (i < NN) g_rowptr[i] = s[threadIdx.x] - v;
    if (threadIdx.x == 1023) g_bsum[blockIdx.x] = s[1023];
}

__global__ void k_scan2() {
    __shared__ int s[128];
    int t = threadIdx.x;
    int v = (t < NBLK) ? g_bsum[t] : 0;
    s[t] = v;
    __syncthreads();
    for (int off = 1; off < 128; off <<= 1) {
        int u = (t >= off) ? s[t - off] : 0;
        __syncthreads();
        s[t] += u;
        __syncthreads();
    }
    if (t < NBLK) g_bsum[t] = s[t] - v;
}

__global__ void k_scan3() {
    int i = blockIdx.x * blockDim.x + threadIdx.x;
    if (i == 0) g_rowptr[NN] = ET;
    if (i >= NN) return;
    int r = g_rowptr[i] + g_bsum[i >> 10];
    g_rowptr[i] = r;
    g_cursor[i] = r;
    g_dinv[i]   = rsqrtf((float)g_cnt[i]);
}

__global__ void k_fill(const int* __restrict__ ei) {
    int e = blockIdx.x * blockDim.x + threadIdx.x;
    if (e >= ET) return;
    int s, d;
    if (e < NE) { s = ei[e]; d = ei[NE + e]; } else { s = e - NE; d = s; }
    int pos = atomicAdd(&g_cursor[d], 1);
    g_col[pos] = s;
}

// ---------------- GEMM1 (round-6 config) : g_hs1 = fp16(x @ W1) raw ------
#define AST 36
#define SA_W (256 * AST)
#define SB_W 2560
#define GEMM_SMEM ((2 * SA_W + 2 * SB_W) * 4)   // 94208

__global__ __launch_bounds__(256) void k_gemm1_mma(const float* __restrict__ x) {
    extern __shared__ float sm[];
    float* sA[2] = {sm, sm + SA_W};
    float* sB[2] = {sm + 2 * SA_W, sm + 2 * SA_W + SB_W};
    int t = threadIdx.x;
    int wid = t >> 5, lane = t & 31;
    int g = lane >> 2, tig = lane & 3;
    int row0 = blockIdx.x * 256 + wid * 32;

    float c[2][8][4];
#pragma unroll
    for (int m = 0; m < 2; m++)
#pragma unroll
        for (int j = 0; j < 8; j++)
#pragma unroll
            for (int q = 0; q < 4; q++) c[m][j][q] = 0.f;

    int arow = t >> 3, ajj = t & 7;
    int argl = blockIdx.x * 256 + arow;

    {
#pragma unroll
        for (int p = 0; p < 8; p++) {
            int row = p * 32 + arow;
            int rg = argl + p * 32; if (rg >= NN) rg = NN - 1;
            cpa16(&sA[0][row * AST + ajj * 4], &x[(size_t)rg * DIN + ajj * 4]);
        }
#pragma unroll
        for (int q = 0; q < 3; q++) {
            int i = q * 256 + t;
            if (i < 640) cpa16(&sB[0][i * 4], &g_bpk[i * 4]);
        }
        cpa_commit();
    }

    for (int ch = 0; ch < 16; ch++) {
        int st = ch & 1;
        if (ch < 15) {
            int cn = ch + 1, sn = cn & 1;
#pragma unroll
            for (int p = 0; p < 8; p++) {
                int row = p * 32 + arow;
                int rg = argl + p * 32; if (rg >= NN) rg = NN - 1;
                cpa16(&sA[sn][row * AST + ajj * 4], &x[(size_t)rg * DIN + cn * 32 + ajj * 4]);
            }
#pragma unroll
            for (int q = 0; q < 3; q++) {
                int i = q * 256 + t;
                if (i < 640) cpa16(&sB[sn][i * 4], &g_bpk[cn * SB_W + i * 4]);
            }
            cpa_commit();
            cpa_wait<1>();
        } else {
            cpa_wait<0>();
        }
        __syncthreads();

        const float* A = sA[st];
        const float* B = sB[st];
#pragma unroll
        for (int s = 0; s < 4; s++) {
            uint32_t a[2][4];
#pragma unroll
            for (int m = 0; m < 2; m++) {
                int r0 = wid * 32 + m * 16 + g;
                a[m][0] = f2tf32(A[r0 * AST + s * 8 + tig]);
                a[m][1] = f2tf32(A[(r0 + 8) * AST + s * 8 + tig]);
                a[m][2] = f2tf32(A[r0 * AST + s * 8 + tig + 4]);
                a[m][3] = f2tf32(A[(r0 + 8) * AST + s * 8 + tig + 4]);
            }
            const float4* bp = (const float4*)&B[(s * 32 + lane) * 20];
            float4 q0 = bp[0], q1 = bp[1], q2 = bp[2], q3 = bp[3];
            uint32_t b0[8] = {__float_as_uint(q0.x), __float_as_uint(q0.y),
                              __float_as_uint(q0.z), __float_as_uint(q0.w),
                              __float_as_uint(q1.x), __float_as_uint(q1.y),
                              __float_as_uint(q1.z), __float_as_uint(q1.w)};
            uint32_t b1[8] = {__float_as_uint(q2.x), __float_as_uint(q2.y),
                              __float_as_uint(q2.z), __float_as_uint(q2.w),
                              __float_as_uint(q3.x), __float_as_uint(q3.y),
                              __float_as_uint(q3.z), __float_as_uint(q3.w)};
#pragma unroll
            for (int j = 0; j < 8; j++) {
#pragma unroll
                for (int m = 0; m < 2; m++) {
                    asm volatile(
                        "mma.sync.aligned.m16n8k8.row.col.f32.tf32.tf32.f32 "
                        "{%0,%1,%2,%3}, {%4,%5,%6,%7}, {%8,%9}, {%0,%1,%2,%3};"
                        : "+f"(c[m][j][0]), "+f"(c[m][j][1]),
                          "+f"(c[m][j][2]), "+f"(c[m][j][3])
                        : "r"(a[m][0]), "r"(a[m][1]), "r"(a[m][2]), "r"(a[m][3]),
                          "r"(b0[j]), "r"(b1[j]));
                }
            }
        }
        __syncthreads();
    }

    // epilogue: raw fp16 store (dinv applied by k_scale1 after CSR join)
#pragma unroll
    for (int m = 0; m < 2; m++) {
        int rA = row0 + m * 16 + g;
        int rB = rA + 8;
#pragma unroll
        for (int j = 0; j < 8; j++) {
            int col = j * 8 + 2 * tig;
            if (rA < NN) {
                __half2 v = __floats2half2_rn(c[m][j][0], c[m][j][1]);
                *(__half2*)&g_hs1[(size_t)rA * DH + col] = v;
            }
            if (rB < NN) {
                __half2 v = __floats2half2_rn(c[m][j][2], c[m][j][3]);
                *(__half2*)&g_hs1[(size_t)rB * DH + col] = v;
            }
        }
    }
}

// ---------------- scale hs1 by dinv (after CSR join) ----------------
__global__ void k_scale1() {
    int i = blockIdx.x * blockDim.x + threadIdx.x;   // one uint4 = 8 halves
    if (i >= NN * DH / 8) return;
    float di = g_dinv[i >> 3];
    __half2* p = (__half2*)&g_hs1[(size_t)i * 8];
#pragma unroll
    for (int q = 0; q < 4; q++) {
        float2 v = __half22float2(p[q]);
        p[q] = __floats2half2_rn(v.x * di, v.y * di);
    }
}

// ---------------- gather-sum (R9 version) ----------------
template <int MODE>
__global__ __launch_bounds__(256) void k_aggsum(const float* __restrict__ bpre) {
    int t = threadIdx.x;
    int lane = t & 31;
    int node = blockIdx.x * 8 + (t >> 5);
    if (node >= NN) return;

    const __half* __restrict__ hin = (MODE == 0) ? g_hs1 : g_hs2;
    int js = g_rowptr[node], je = g_rowptr[node + 1];
    float ax = 0.f, ay = 0.f;
    int j = js;
    for (; j + 32 <= je; j += 32) {
        int myc = g_col[j + lane];
#pragma unroll
        for (int l = 0; l < 32; l++) {
            int s = __shfl_sync(0xffffffffu, myc, l);
            float2 v = __half22float2(*(const __half2*)&hin[s * DH + 2 * lane]);
            ax += v.x; ay += v.y;
        }
    }
    if (j < je) {
        int myc = (j + lane < je) ? g_col[j + lane] : 0;
        int m = je - j;
        for (int l = 0; l < m; l++) {
            int s = __shfl_sync(0xffffffffu, myc, l);
            float2 v = __half22float2(*(const __half2*)&hin[s * DH + 2 * lane]);
            ax += v.x; ay += v.y;
        }
    }

    float di = g_dinv[node];
    float2 bp = ((const float2*)bpre)[lane];
    ax = ax * di + bp.x;
    ay = ay * di + bp.y;
    if (MODE == 0) { ax = fmaxf(ax, 0.f); ay = fmaxf(ay, 0.f); }
    float2 o = {ax, ay};
    *(float2*)&g_a[(size_t)node * DH + 2 * lane] = o;
}

// ---------------- mm64 with SMEM-staged A (R9 version) ----------------
#define FAST 68
#define MM64_SMEM ((256 * FAST + 8 * 32 * 20) * 4)   // 90112

template <int MODE>
__global__ __launch_bounds__(256) void k_mm64(const float* __restrict__ bpost,
                                              float* __restrict__ out) {
    extern __shared__ float sm2[];
    float* aS = sm2;
    float* sB = sm2 + 256 * FAST;
    int t = threadIdx.x;
    int wid = t >> 5, lane = t & 31;
    int g = lane >> 2, tig = lane & 3;
    int base = blockIdx.x * 256;
    int w32 = wid * 32;

    {
        const float4* src = (const float4*)&g_bpk[(64 + MODE * 8) * 640];
        float4* dst = (float4*)sB;
#pragma unroll
        for (int i = 0; i < 5; i++) dst[t + i * 256] = src[t + i * 256];
    }
#pragma unroll
    for (int i = 0; i < 16; i++) {
        int lr = i * 16 + (t >> 4);
        int rg = base + lr; if (rg >= NN) rg = NN - 1;
        float4 v = *(const float4*)&g_a[(size_t)rg * DH + (t & 15) * 4];
        *(float4*)&aS[lr * FAST + (t & 15) * 4] = v;
    }
    __syncthreads();

    float c[2][8][4];
#pragma unroll
    for (int m = 0; m < 2; m++)
#pragma unroll
        for (int j = 0; j < 8; j++)
#pragma unroll
            for (int q = 0; q < 4; q++) c[m][j][q] = 0.f;

#pragma unroll
    for (int s = 0; s < 8; s++) {
        int k0 = s * 8;
        uint32_t a[2][4];
#pragma unroll
        for (int m = 0; m < 2; m++) {
            int r0 = w32 + m * 16 + g;
            a[m][0] = f2tf32(aS[r0 * FAST + k0 + tig]);
            a[m][1] = f2tf32(aS[(r0 + 8) * FAST + k0 + tig]);
            a[m][2] = f2tf32(aS[r0 * FAST + k0 + tig + 4]);
            a[m][3] = f2tf32(aS[(r0 + 8) * FAST + k0 + tig + 4]);
        }
        const float4* bpf = (const float4*)&sB[(s * 32 + lane) * 20];
        float4 q0 = bpf[0], q1 = bpf[1], q2 = bpf[2], q3 = bpf[3];
        uint32_t b0[8] = {__float_as_uint(q0.x), __float_as_uint(q0.y),
                          __float_as_uint(q0.z), __float_as_uint(q0.w),
                          __float_as_uint(q1.x), __float_as_uint(q1.y),
                          __float_as_uint(q1.z), __float_as_uint(q1.w)};
        uint32_t b1[8] = {__float_as_uint(q2.x), __float_as_uint(q2.y),
                          __float_as_uint(q2.z), __float_as_uint(q2.w),
                          __float_as_uint(q3.x), __float_as_uint(q3.y),
                          __float_as_uint(q3.z), __float_as_uint(q3.w)};
#pragma unroll
        for (int j = 0; j < 8; j++) {
#pragma unroll
            for (int m = 0; m < 2; m++) {
                asm volatile(
                    "mma.sync.aligned.m16n8k8.row.col.f32.tf32.tf32.f32 "
                    "{%0,%1,%2,%3}, {%4,%5,%6,%7}, {%8,%9}, {%0,%1,%2,%3};"
                    : "+f"(c[m][j][0]), "+f"(c[m][j][1]),
                      "+f"(c[m][j][2]), "+f"(c[m][j][3])
                    : "r"(a[m][0]), "r"(a[m][1]), "r"(a[m][2]), "r"(a[m][3]),
                      "r"(b0[j]), "r"(b1[j]));
            }
        }
    }

    if (MODE == 0) {
#pragma unroll
        for (int m = 0; m < 2; m++) {
            int rA = base + w32 + m * 16 + g, rB = rA + 8;
            float diA = g_dinv[(rA < NN) ? rA : (NN - 1)];
            float diB = g_dinv[(rB < NN) ? rB : (NN - 1)];
#pragma unroll
            for (int j = 0; j < 8; j++) {
                int col = j * 8 + 2 * tig;
                if (rA < NN) {
                    __half2 v = __floats2half2_rn(c[m][j][0] * diA, c[m][j][1] * diA);
                    *(__half2*)&g_hs2[(size_t)rA * DH + col] = v;
                }
                if (rB < NN) {
                    __half2 v = __floats2half2_rn(c[m][j][2] * diB, c[m][j][3] * diB);
                    *(__half2*)&g_hs2[(size_t)rB * DH + col] = v;
                }
            }
        }
    } else {
#pragma unroll
        for (int m = 0; m < 2; m++) {
            int rA = base + w32 + m * 16 + g, rB = rA + 8;
#pragma unroll
            for (int j = 0; j < 8; j++) {
                int col = j * 8 + 2 * tig;
                float2 bq = *(const float2*)&bpost[col];
                if (rA < NN) {
                    float2 v = {c[m][j][0] + bq.x, c[m][j][1] + bq.y};
                    *(float2*)&out[(size_t)rA * DH + col] = v;
                }
                if (rB < NN) {
                    float2 v = {c[m][j][2] + bq.x, c[m][j][3] + bq.y};
                    *(float2*)&out[(size_t)rB * DH + col] = v;
                }
            }
        }
    }
}

// ---------------- launch ----------------
extern "C" void kernel_launch(void* const* d_in, const int* in_sizes, int n_in,
                              void* d_out, int out_size) {
    const float* x    = (const float*)d_in[0];
    const int*   ei   = (const int*)d_in[1];
    const float* W1   = (const float*)d_in[2];
    const float* b1   = (const float*)d_in[3];
    const float* W2   = (const float*)d_in[4];
    const float* b2   = (const float*)d_in[5];
    const float* Wlin = (const float*)d_in[6];
    const float* blin = (const float*)d_in[7];
    float* out = (float*)d_out;

    static cudaStream_t s2 = nullptr;
    static cudaEvent_t e0 = nullptr, e2 = nullptr;
    if (!s2) {   // created on the uncaptured correctness call
        cudaFuncSetAttribute(k_gemm1_mma, cudaFuncAttributeMaxDynamicSharedMemorySize, GEMM_SMEM);
        cudaFuncSetAttribute(k_mm64<0>, cudaFuncAttributeMaxDynamicSharedMemorySize, MM64_SMEM);
        cudaFuncSetAttribute(k_mm64<1>, cudaFuncAttributeMaxDynamicSharedMemorySize, MM64_SMEM);
        cudaStreamCreateWithFlags(&s2, cudaStreamNonBlocking);
        cudaEventCreateWithFlags(&e0, cudaEventDisableTiming);
        cudaEventCreateWithFlags(&e2, cudaEventDisableTiming);
    }

    // fork s2 from capture origin; GEMM has no CSR dependency
    cudaEventRecord(e0, 0);
    cudaStreamWaitEvent(s2, e0, 0);

    k_pack <<<160, 256>>>(W1, W2, Wlin);                       // #0 (main)
    k_init <<<(NN + 255) / 256, 256, 0, s2>>>();               // #1 (s2)
    k_count<<<(ET + 255) / 256, 256, 0, s2>>>(ei);             // #2 (s2)
    k_gemm1_mma<<<(NN + 255) / 256, 256, GEMM_SMEM>>>(x);      // #3 (main) <- ncu
    k_scan1<<<NBLK, 1024, 0, s2>>>();                          // #4 (s2)
    k_scan2<<<1, 128, 0, s2>>>();                              // #5 (s2)
    k_scan3<<<(NN + 255) / 256, 256, 0, s2>>>();               // #6 (s2)
    k_fill <<<(ET + 255) / 256, 256, 0, s2>>>(ei);             // #7 (s2)
    cudaEventRecord(e2, s2);
    cudaStreamWaitEvent(0, e2, 0);                             // join

    k_scale1<<<(NN * DH / 8 + 255) / 256, 256>>>();            // #8
    k_aggsum<0><<<NN / 8 + 1, 256>>>(b1);                      // #9
    k_mm64<0><<<(NN + 255) / 256, 256, MM64_SMEM>>>(nullptr, nullptr);  // #10
    k_aggsum<1><<<NN / 8 + 1, 256>>>(b2);                      // #11
    k_mm64<1><<<(NN + 255) / 256, 256, MM64_SMEM>>>(blin, out);         // #12
}

// round 16
// speedup vs baseline: 1.0794x; 1.0208x over previous
#include <cuda_runtime.h>
#include <cuda_fp16.h>
#include <cstdint>

#define NN 100000
#define NE 3200000
#define ET (NE + NN)
#define DIN 512
#define DH 64
#define NBLK 98

__device__ __half g_hs1[(size_t)NN * DH];   // fp16: x@W1 (raw; scaled by k_scale1)
__device__ __half g_hs2[(size_t)NN * DH];   // fp16: dinv*(a@W2)
__device__ float g_a[(size_t)NN * DH];
__device__ float g_bpk[80 * 32 * 20];
__device__ float g_dinv[NN];
__device__ int   g_cnt[NN];
__device__ int   g_rowptr[NN + 1];
__device__ int   g_cursor[NN];
__device__ int   g_col[ET];
__device__ int   g_bsum[128];

__device__ __forceinline__ uint32_t smem_u32(const void* p) {
    uint32_t a;
    asm("{ .reg .u64 t; cvta.to.shared.u64 t, %1; cvt.u32.u64 %0, t; }" : "=r"(a) : "l"(p));
    return a;
}
__device__ __forceinline__ void cpa16(float* dst, const float* src) {
    uint32_t d = smem_u32(dst);
    asm volatile("cp.async.ca.shared.global [%0], [%1], 16;" :: "r"(d), "l"(src) : "memory");
}
__device__ __forceinline__ void cpa_commit() {
    asm volatile("cp.async.commit_group;" ::: "memory");
}
template <int N> __device__ __forceinline__ void cpa_wait() {
    asm volatile("cp.async.wait_group %0;" :: "n"(N) : "memory");
}
__device__ __forceinline__ uint32_t f2tf32(float f) {
    uint32_t u;
    asm("cvt.rna.tf32.f32 %0, %1;" : "=r"(u) : "f"(f));
    return u;
}

__global__ void k_pack(const float* __restrict__ W1, const float* __restrict__ W2,
                       const float* __restrict__ Wlin) {
    int tid = blockIdx.x * blockDim.x + threadIdx.x;
    if (tid >= 80 * 32 * 16) return;
    int s   = tid >> 9;
    int l   = (tid >> 4) & 31;
    int idx = tid & 15;
    int g = l >> 2, tig = l & 3;
    int j = idx & 7;
    int half = idx >> 3;
    const float* W; int sl;
    if (s < 64)      { W = W1;   sl = s; }
    else if (s < 72) { W = W2;   sl = s - 64; }
    else             { W = Wlin; sl = s - 72; }
    int k = sl * 8 + tig + half * 4;
    float v = W[k * DH + 8 * j + g];
    g_bpk[(s * 32 + l) * 20 + idx] = __uint_as_float(f2tf32(v));
}

__global__ void k_init() {
    int i = blockIdx.x * blockDim.x + threadIdx.x;
    if (i < NN) g_cnt[i] = 0;
}

__global__ void k_count(const int* __restrict__ ei) {
    int e = blockIdx.x * blockDim.x + threadIdx.x;
    if (e >= ET) return;
    int d = (e < NE) ? ei[NE + e] : (e - NE);
    atomicAdd(&g_cnt[d], 1);
}

__global__ void k_scan1() {
    __shared__ int s[1024];
    int i = blockIdx.x * 1024 + threadIdx.x;
    int v = (i < NN) ? g_cnt[i] : 0;
    s[threadIdx.x] = v;
    __syncthreads();
    for (int off = 1; off < 1024; off <<= 1) {
        int t = (threadIdx.x >= off) ? s[threadIdx.x - off] : 0;
        __syncthreads();
        s[threadIdx.x] += t;
        __syncthreads();
    }
    if (i < NN) g_rowptr[i] = s[threadIdx.x] - v;
    if (threadIdx.x == 1023) g_bsum[blockIdx.x] = s[1023];
}

__global__ void k_scan2() {
    __shared__ int s[128];
    int t = threadIdx.x;
    int v = (t < NBLK) ? g_bsum[t] : 0;
    s[t] = v;
    __syncthreads();
    for (int off = 1; off < 128; off <<= 1) {
        int u = (t >= off) ? s[t - off] : 0;
        __syncthreads();
        s[t] += u;
        __syncthreads();
    }
    if (t < NBLK) g_bsum[t] = s[t] - v;
}

__global__ void k_scan3() {
    int i = blockIdx.x * blockDim.x + threadIdx.x;
    if (i == 0) g_rowptr[NN] = ET;
    if (i >= NN) return;
    int r = g_rowptr[i] + g_bsum[i >> 10];
    g_rowptr[i] = r;
    g_cursor[i] = r;
    g_dinv[i]   = rsqrtf((float)g_cnt[i]);
}

__global__ void k_fill(const int* __restrict__ ei) {
    int e = blockIdx.x * blockDim.x + threadIdx.x;
    if (e >= ET) return;
    int s, d;
    if (e < NE) { s = ei[e]; d = ei[NE + e]; } else { s = e - NE; d = s; }
    int pos = atomicAdd(&g_cursor[d], 1);
    g_col[pos] = s;
}

// ---------------- GEMM1 (round-6 config) : g_hs1 = fp16(x @ W1) raw ------
#define AST 36
#define SA_W (256 * AST)
#define SB_W 2560
#define GEMM_SMEM ((2 * SA_W + 2 * SB_W) * 4)   // 94208

__global__ __launch_bounds__(256) void k_gemm1_mma(const float* __restrict__ x) {
    extern __shared__ float sm[];
    float* sA[2] = {sm, sm + SA_W};
    float* sB[2] = {sm + 2 * SA_W, sm + 2 * SA_W + SB_W};
    int t = threadIdx.x;
    int wid = t >> 5, lane = t & 31;
    int g = lane >> 2, tig = lane & 3;
    int row0 = blockIdx.x * 256 + wid * 32;

    float c[2][8][4];
#pragma unroll
    for (int m = 0; m < 2; m++)
#pragma unroll
        for (int j = 0; j < 8; j++)
#pragma unroll
            for (int q = 0; q < 4; q++) c[m][j][q] = 0.f;

    int arow = t >> 3, ajj = t & 7;
    int argl = blockIdx.x * 256 + arow;

    {
#pragma unroll
        for (int p = 0; p < 8; p++) {
            int row = p * 32 + arow;
            int rg = argl + p * 32; if (rg >= NN) rg = NN - 1;
            cpa16(&sA[0][row * AST + ajj * 4], &x[(size_t)rg * DIN + ajj * 4]);
        }
#pragma unroll
        for (int q = 0; q < 3; q++) {
            int i = q * 256 + t;
            if (i < 640) cpa16(&sB[0][i * 4], &g_bpk[i * 4]);
        }
        cpa_commit();
    }

    for (int ch = 0; ch < 16; ch++) {
        int st = ch & 1;
        if (ch < 15) {
            int cn = ch + 1, sn = cn & 1;
#pragma unroll
            for (int p = 0; p < 8; p++) {
                int row = p * 32 + arow;
                int rg = argl + p * 32; if (rg >= NN) rg = NN - 1;
                cpa16(&sA[sn][row * AST + ajj * 4], &x[(size_t)rg * DIN + cn * 32 + ajj * 4]);
            }
#pragma unroll
            for (int q = 0; q < 3; q++) {
                int i = q * 256 + t;
                if (i < 640) cpa16(&sB[sn][i * 4], &g_bpk[cn * SB_W + i * 4]);
            }
            cpa_commit();
            cpa_wait<1>();
        } else {
            cpa_wait<0>();
        }
        __syncthreads();

        const float* A = sA[st];
        const float* B = sB[st];
#pragma unroll
        for (int s = 0; s < 4; s++) {
            uint32_t a[2][4];
#pragma unroll
            for (int m = 0; m < 2; m++) {
                int r0 = wid * 32 + m * 16 + g;
                a[m][0] = f2tf32(A[r0 * AST + s * 8 + tig]);
                a[m][1] = f2tf32(A[(r0 + 8) * AST + s * 8 + tig]);
                a[m][2] = f2tf32(A[r0 * AST + s * 8 + tig + 4]);
                a[m][3] = f2tf32(A[(r0 + 8) * AST + s * 8 + tig + 4]);
            }
            const float4* bp = (const float4*)&B[(s * 32 + lane) * 20];
            float4 q0 = bp[0], q1 = bp[1], q2 = bp[2], q3 = bp[3];
            uint32_t b0[8] = {__float_as_uint(q0.x), __float_as_uint(q0.y),
                              __float_as_uint(q0.z), __float_as_uint(q0.w),
                              __float_as_uint(q1.x), __float_as_uint(q1.y),
                              __float_as_uint(q1.z), __float_as_uint(q1.w)};
            uint32_t b1[8] = {__float_as_uint(q2.x), __float_as_uint(q2.y),
                              __float_as_uint(q2.z), __float_as_uint(q2.w),
                              __float_as_uint(q3.x), __float_as_uint(q3.y),
                              __float_as_uint(q3.z), __float_as_uint(q3.w)};
#pragma unroll
            for (int j = 0; j < 8; j++) {
#pragma unroll
                for (int m = 0; m < 2; m++) {
                    asm volatile(
                        "mma.sync.aligned.m16n8k8.row.col.f32.tf32.tf32.f32 "
                        "{%0,%1,%2,%3}, {%4,%5,%6,%7}, {%8,%9}, {%0,%1,%2,%3};"
                        : "+f"(c[m][j][0]), "+f"(c[m][j][1]),
                          "+f"(c[m][j][2]), "+f"(c[m][j][3])
                        : "r"(a[m][0]), "r"(a[m][1]), "r"(a[m][2]), "r"(a[m][3]),
                          "r"(b0[j]), "r"(b1[j]));
                }
            }
        }
        __syncthreads();
    }

    // epilogue: raw fp16 store (dinv applied by k_scale1 after CSR join)
#pragma unroll
    for (int m = 0; m < 2; m++) {
        int rA = row0 + m * 16 + g;
        int rB = rA + 8;
#pragma unroll
        for (int j = 0; j < 8; j++) {
            int col = j * 8 + 2 * tig;
            if (rA < NN) {
                __half2 v = __floats2half2_rn(c[m][j][0], c[m][j][1]);
                *(__half2*)&g_hs1[(size_t)rA * DH + col] = v;
            }
            if (rB < NN) {
                __half2 v = __floats2half2_rn(c[m][j][2], c[m][j][3]);
                *(__half2*)&g_hs1[(size_t)rB * DH + col] = v;
            }
        }
    }
}

// ---------------- scale hs1 by dinv (after CSR join) ----------------
__global__ void k_scale1() {
    int i = blockIdx.x * blockDim.x + threadIdx.x;   // one uint4 = 8 halves
    if (i >= NN * DH / 8) return;
    float di = g_dinv[i >> 3];
    __half2* p = (__half2*)&g_hs1[(size_t)i * 8];
#pragma unroll
    for (int q = 0; q < 4; q++) {
        float2 v = __half22float2(p[q]);
        p[q] = __floats2half2_rn(v.x * di, v.y * di);
    }
}

// ---------------- gather-sum: LDG.128, 4 edges per warp-iteration --------
// lane = q*8 + fl : q = edge slot (0..3), fl = feature octet (0..7).
// Each lane accumulates 8 features in fp32; cross-q shfl reduction at end.
template <int MODE>
__global__ __launch_bounds__(256) void k_aggsum(const float* __restrict__ bpre) {
    int t = threadIdx.x;
    int lane = t & 31;
    int q = lane >> 3;
    int fl = lane & 7;
    int node = blockIdx.x * 8 + (t >> 5);
    if (node >= NN) return;

    const __half* __restrict__ hin = (MODE == 0) ? g_hs1 : g_hs2;
    int js = g_rowptr[node], je = g_rowptr[node + 1];
    float a0 = 0.f, a1 = 0.f, a2 = 0.f, a3 = 0.f;
    float a4 = 0.f, a5 = 0.f, a6 = 0.f, a7 = 0.f;
    int j = js;
    for (; j + 32 <= je; j += 32) {
        int myc = g_col[j + lane];
#pragma unroll
        for (int l = 0; l < 8; l++) {
            int s = __shfl_sync(0xffffffffu, myc, 4 * l + q);
            uint4 raw = *(const uint4*)&hin[s * DH + fl * 8];
            float2 v0 = __half22float2(*(__half2*)&raw.x);
            float2 v1 = __half22float2(*(__half2*)&raw.y);
            float2 v2 = __half22float2(*(__half2*)&raw.z);
            float2 v3 = __half22float2(*(__half2*)&raw.w);
            a0 += v0.x; a1 += v0.y; a2 += v1.x; a3 += v1.y;
            a4 += v2.x; a5 += v2.y; a6 += v3.x; a7 += v3.y;
        }
    }
    if (j < je) {
        int m = je - j;
        int myc = (j + lane < je) ? g_col[j + lane] : 0;
        int iters = (m + 3) >> 2;
        for (int l = 0; l < iters; l++) {
            int e = 4 * l + q;
            int s = __shfl_sync(0xffffffffu, myc, e);
            if (e < m) {
                uint4 raw = *(const uint4*)&hin[s * DH + fl * 8];
                float2 v0 = __half22float2(*(__half2*)&raw.x);
                float2 v1 = __half22float2(*(__half2*)&raw.y);
                float2 v2 = __half22float2(*(__half2*)&raw.z);
                float2 v3 = __half22float2(*(__half2*)&raw.w);
                a0 += v0.x; a1 += v0.y; a2 += v1.x; a3 += v1.y;
                a4 += v2.x; a5 += v2.y; a6 += v3.x; a7 += v3.y;
            }
        }
    }

    // reduce across the 4 q-groups (lanes fl, fl+8, fl+16, fl+24)
#define RED1(v) v += __shfl_down_sync(0xffffffffu, v, 16); \
                v += __shfl_down_sync(0xffffffffu, v, 8);
    RED1(a0) RED1(a1) RED1(a2) RED1(a3) RED1(a4) RED1(a5) RED1(a6) RED1(a7)
#undef RED1

    if (lane < 8) {
        float di = g_dinv[node];
        float4 b0 = *(const float4*)&bpre[fl * 8];
        float4 b1 = *(const float4*)&bpre[fl * 8 + 4];
        a0 = a0 * di + b0.x; a1 = a1 * di + b0.y;
        a2 = a2 * di + b0.z; a3 = a3 * di + b0.w;
        a4 = a4 * di + b1.x; a5 = a5 * di + b1.y;
        a6 = a6 * di + b1.z; a7 = a7 * di + b1.w;
        if (MODE == 0) {
            a0 = fmaxf(a0, 0.f); a1 = fmaxf(a1, 0.f);
            a2 = fmaxf(a2, 0.f); a3 = fmaxf(a3, 0.f);
            a4 = fmaxf(a4, 0.f); a5 = fmaxf(a5, 0.f);
            a6 = fmaxf(a6, 0.f); a7 = fmaxf(a7, 0.f);
        }
        float4 o0 = {a0, a1, a2, a3};
        float4 o1 = {a4, a5, a6, a7};
        *(float4*)&g_a[(size_t)node * DH + fl * 8]     = o0;
        *(float4*)&g_a[(size_t)node * DH + fl * 8 + 4] = o1;
    }
}

// ---------------- mm64 with SMEM-staged A (R9 version) ----------------
#define FAST 68
#define MM64_SMEM ((256 * FAST + 8 * 32 * 20) * 4)   // 90112

template <int MODE>
__global__ __launch_bounds__(256) void k_mm64(const float* __restrict__ bpost,
                                              float* __restrict__ out) {
    extern __shared__ float sm2[];
    float* aS = sm2;
    float* sB = sm2 + 256 * FAST;
    int t = threadIdx.x;
    int wid = t >> 5, lane = t & 31;
    int g = lane >> 2, tig = lane & 3;
    int base = blockIdx.x * 256;
    int w32 = wid * 32;

    {
        const float4* src = (const float4*)&g_bpk[(64 + MODE * 8) * 640];
        float4* dst = (float4*)sB;
#pragma unroll
        for (int i = 0; i < 5; i++) dst[t + i * 256] = src[t + i * 256];
    }
#pragma unroll
    for (int i = 0; i < 16; i++) {
        int lr = i * 16 + (t >> 4);
        int rg = base + lr; if (rg >= NN) rg = NN - 1;
        float4 v = *(const float4*)&g_a[(size_t)rg * DH + (t & 15) * 4];
        *(float4*)&aS[lr * FAST + (t & 15) * 4] = v;
    }
    __syncthreads();

    float c[2][8][4];
#pragma unroll
    for (int m = 0; m < 2; m++)
#pragma unroll
        for (int j = 0; j < 8; j++)
#pragma unroll
            for (int q = 0; q < 4; q++) c[m][j][q] = 0.f;

#pragma unroll
    for (int s = 0; s < 8; s++) {
        int k0 = s * 8;
        uint32_t a[2][4];
#pragma unroll
        for (int m = 0; m < 2; m++) {
            int r0 = w32 + m * 16 + g;
            a[m][0] = f2tf32(aS[r0 * FAST + k0 + tig]);
            a[m][1] = f2tf32(aS[(r0 + 8) * FAST + k0 + tig]);
            a[m][2] = f2tf32(aS[r0 * FAST + k0 + tig + 4]);
            a[m][3] = f2tf32(aS[(r0 + 8) * FAST + k0 + tig + 4]);
        }
        const float4* bpf = (const float4*)&sB[(s * 32 + lane) * 20];
        float4 q0 = bpf[0], q1 = bpf[1], q2 = bpf[2], q3 = bpf[3];
        uint32_t b0[8] = {__float_as_uint(q0.x), __float_as_uint(q0.y),
                          __float_as_uint(q0.z), __float_as_uint(q0.w),
                          __float_as_uint(q1.x), __float_as_uint(q1.y),
                          __float_as_uint(q1.z), __float_as_uint(q1.w)};
        uint32_t b1[8] = {__float_as_uint(q2.x), __float_as_uint(q2.y),
                          __float_as_uint(q2.z), __float_as_uint(q2.w),
                          __float_as_uint(q3.x), __float_as_uint(q3.y),
                          __float_as_uint(q3.z), __float_as_uint(q3.w)};
#pragma unroll
        for (int j = 0; j < 8; j++) {
#pragma unroll
            for (int m = 0; m < 2; m++) {
                asm volatile(
                    "mma.sync.aligned.m16n8k8.row.col.f32.tf32.tf32.f32 "
                    "{%0,%1,%2,%3}, {%4,%5,%6,%7}, {%8,%9}, {%0,%1,%2,%3};"
                    : "+f"(c[m][j][0]), "+f"(c[m][j][1]),
                      "+f"(c[m][j][2]), "+f"(c[m][j][3])
                    : "r"(a[m][0]), "r"(a[m][1]), "r"(a[m][2]), "r"(a[m][3]),
                      "r"(b0[j]), "r"(b1[j]));
            }
        }
    }

    if (MODE == 0) {
#pragma unroll
        for (int m = 0; m < 2; m++) {
            int rA = base + w32 + m * 16 + g, rB = rA + 8;
            float diA = g_dinv[(rA < NN) ? rA : (NN - 1)];
            float diB = g_dinv[(rB < NN) ? rB : (NN - 1)];
#pragma unroll
            for (int j = 0; j < 8; j++) {
                int col = j * 8 + 2 * tig;
                if (rA < NN) {
                    __half2 v = __floats2half2_rn(c[m][j][0] * diA, c[m][j][1] * diA);
                    *(__half2*)&g_hs2[(size_t)rA * DH + col] = v;
                }
                if (rB < NN) {
                    __half2 v = __floats2half2_rn(c[m][j][2] * diB, c[m][j][3] * diB);
                    *(__half2*)&g_hs2[(size_t)rB * DH + col] = v;
                }
            }
        }
    } else {
#pragma unroll
        for (int m = 0; m < 2; m++) {
            int rA = base + w32 + m * 16 + g, rB = rA + 8;
#pragma unroll
            for (int j = 0; j < 8; j++) {
                int col = j * 8 + 2 * tig;
                float2 bq = *(const float2*)&bpost[col];
                if (rA < NN) {
                    float2 v = {c[m][j][0] + bq.x, c[m][j][1] + bq.y};
                    *(float2*)&out[(size_t)rA * DH + col] = v;
                }
                if (rB < NN) {
                    float2 v = {c[m][j][2] + bq.x, c[m][j][3] + bq.y};
                    *(float2*)&out[(size_t)rB * DH + col] = v;
                }
            }
        }
    }
}

// ---------------- launch ----------------
extern "C" void kernel_launch(void* const* d_in, const int* in_sizes, int n_in,
                              void* d_out, int out_size) {
    const float* x    = (const float*)d_in[0];
    const int*   ei   = (const int*)d_in[1];
    const float* W1   = (const float*)d_in[2];
    const float* b1   = (const float*)d_in[3];
    const float* W2   = (const float*)d_in[4];
    const float* b2   = (const float*)d_in[5];
    const float* Wlin = (const float*)d_in[6];
    const float* blin = (const float*)d_in[7];
    float* out = (float*)d_out;

    static cudaStream_t s2 = nullptr;
    static cudaEvent_t e0 = nullptr, e2 = nullptr;
    if (!s2) {   // created on the uncaptured correctness call
        cudaFuncSetAttribute(k_gemm1_mma, cudaFuncAttributeMaxDynamicSharedMemorySize, GEMM_SMEM);
        cudaFuncSetAttribute(k_mm64<0>, cudaFuncAttributeMaxDynamicSharedMemorySize, MM64_SMEM);
        cudaFuncSetAttribute(k_mm64<1>, cudaFuncAttributeMaxDynamicSharedMemorySize, MM64_SMEM);
        cudaStreamCreateWithFlags(&s2, cudaStreamNonBlocking);
        cudaEventCreateWithFlags(&e0, cudaEventDisableTiming);
        cudaEventCreateWithFlags(&e2, cudaEventDisableTiming);
    }

    // fork s2 from capture origin; GEMM has no CSR dependency
    cudaEventRecord(e0, 0);
    cudaStreamWaitEvent(s2, e0, 0);

    k_pack <<<160, 256>>>(W1, W2, Wlin);                       // #0 (main)
    k_init <<<(NN + 255) / 256, 256, 0, s2>>>();               // #1 (s2)
    k_count<<<(ET + 255) / 256, 256, 0, s2>>>(ei);             // #2 (s2)
    k_gemm1_mma<<<(NN + 255) / 256, 256, GEMM_SMEM>>>(x);      // #3 (main) <- ncu
    k_scan1<<<NBLK, 1024, 0, s2>>>();                          // #4 (s2)
    k_scan2<<<1, 128, 0, s2>>>();                              // #5 (s2)
    k_scan3<<<(NN + 255) / 256, 256, 0, s2>>>();               // #6 (s2)
    k_fill <<<(ET + 255) / 256, 256, 0, s2>>>(ei);             // #7 (s2)
    cudaEventRecord(e2, s2);
    cudaStreamWaitEvent(0, e2, 0);                             // join

    k_scale1<<<(NN * DH / 8 + 255) / 256, 256>>>();            // #8
    k_aggsum<0><<<NN / 8 + 1, 256>>>(b1);                      // #9
    k_mm64<0><<<(NN + 255) / 256, 256, MM64_SMEM>>>(nullptr, nullptr);  // #10
    k_aggsum<1><<<NN / 8 + 1, 256>>>(b2);                      // #11
    k_mm64<1><<<(NN + 255) / 256, 256, MM64_SMEM>>>(blin, out);         // #12
}

// round 17
// speedup vs baseline: 1.1151x; 1.0331x over previous
#include <cuda_runtime.h>
#include <cuda_fp16.h>
#include <cstdint>

#define NN 100000
#define NE 3200000
#define ET (NE + NN)
#define DIN 512
#define DH 64
#define NBLK 98

__device__ __half g_hs1[(size_t)NN * DH];   // fp16: x@W1 (raw; scaled by k_scale1)
__device__ __half g_hs2[(size_t)NN * DH];   // fp16: dinv*(a@W2)
__device__ float g_a[(size_t)NN * DH];
__device__ uint32_t g_bpkh[40 * 32 * 20];   // fp16 half2 B-frags: W1(32 ks) W2(4) Wlin(4)
__device__ float g_dinv[NN];
__device__ int   g_cnt[NN];
__device__ int   g_rowptr[NN + 1];
__device__ int   g_cursor[NN];
__device__ int   g_col[ET];
__device__ int   g_bsum[128];

__device__ __forceinline__ uint32_t smem_u32(const void* p) {
    uint32_t a;
    asm("{ .reg .u64 t; cvta.to.shared.u64 t, %1; cvt.u32.u64 %0, t; }" : "=r"(a) : "l"(p));
    return a;
}
__device__ __forceinline__ void cpa16(void* dst, const void* src) {
    uint32_t d = smem_u32(dst);
    asm volatile("cp.async.ca.shared.global [%0], [%1], 16;" :: "r"(d), "l"(src) : "memory");
}
__device__ __forceinline__ void cpa_commit() {
    asm volatile("cp.async.commit_group;" ::: "memory");
}
template <int N> __device__ __forceinline__ void cpa_wait() {
    asm volatile("cp.async.wait_group %0;" :: "n"(N) : "memory");
}
__device__ __forceinline__ uint32_t f22h2(float x, float y) {
    __half2 h = __floats2half2_rn(x, y);
    return *(uint32_t*)&h;
}

// ---------------- B-frag pack (fp16 m16n8k16): W1/W2/Wlin ----------------
// kstep16 s: lane l (g=l>>2, tig=l&3), idx: j=idx&7 (n-tile), h=idx>>3 (b0/b1)
//   reg = half2( W[16s + 2*tig + 8h][8j+g], W[16s + 2*tig + 8h + 1][8j+g] )
__global__ void k_pack(const float* __restrict__ W1, const float* __restrict__ W2,
                       const float* __restrict__ Wlin) {
    int tid = blockIdx.x * blockDim.x + threadIdx.x;
    if (tid >= 40 * 32 * 16) return;
    int s   = tid >> 9;
    int l   = (tid >> 4) & 31;
    int idx = tid & 15;
    int g = l >> 2, tig = l & 3;
    int j = idx & 7;
    int h = idx >> 3;
    const float* W; int sl;
    if (s < 32)      { W = W1;   sl = s; }
    else if (s < 36) { W = W2;   sl = s - 32; }
    else             { W = Wlin; sl = s - 36; }
    int k = sl * 16 + 2 * tig + 8 * h;
    int col = 8 * j + g;
    g_bpkh[(s * 32 + l) * 20 + idx] = f22h2(W[k * DH + col], W[(k + 1) * DH + col]);
}

// ---------------- CSR build ----------------
__global__ void k_init() {
    int i = blockIdx.x * blockDim.x + threadIdx.x;
    if (i < NN) g_cnt[i] = 0;
}

__global__ void k_count(const int* __restrict__ ei) {
    int e = blockIdx.x * blockDim.x + threadIdx.x;
    if (e >= ET) return;
    int d = (e < NE) ? ei[NE + e] : (e - NE);
    atomicAdd(&g_cnt[d], 1);
}

__global__ void k_scan1() {
    __shared__ int s[1024];
    int i = blockIdx.x * 1024 + threadIdx.x;
    int v = (i < NN) ? g_cnt[i] : 0;
    s[threadIdx.x] = v;
    __syncthreads();
    for (int off = 1; off < 1024; off <<= 1) {
        int t = (threadIdx.x >= off) ? s[threadIdx.x - off] : 0;
        __syncthreads();
        s[threadIdx.x] += t;
        __syncthreads();
    }
    if (i < NN) g_rowptr[i] = s[threadIdx.x] - v;
    if (threadIdx.x == 1023) g_bsum[blockIdx.x] = s[1023];
}

__global__ void k_scan2() {
    __shared__ int s[128];
    int t = threadIdx.x;
    int v = (t < NBLK) ? g_bsum[t] : 0;
    s[t] = v;
    __syncthreads();
    for (int off = 1; off < 128; off <<= 1) {
        int u = (t >= off) ? s[t - off] : 0;
        __syncthreads();
        s[t] += u;
        __syncthreads();
    }
    if (t < NBLK) g_bsum[t] = s[t] - v;
}

__global__ void k_scan3() {
    int i = blockIdx.x * blockDim.x + threadIdx.x;
    if (i == 0) g_rowptr[NN] = ET;
    if (i >= NN) return;
    int r = g_rowptr[i] + g_bsum[i >> 10];
    g_rowptr[i] = r;
    g_cursor[i] = r;
    g_dinv[i]   = rsqrtf((float)g_cnt[i]);
}

__global__ void k_fill(const int* __restrict__ ei) {
    int e = blockIdx.x * blockDim.x + threadIdx.x;
    if (e >= ET) return;
    int s, d;
    if (e < NE) { s = ei[e]; d = ei[NE + e]; } else { s = e - NE; d = s; }
    int pos = atomicAdd(&g_cursor[d], 1);
    g_col[pos] = s;
}

// ---------------- GEMM1 (fp16 MMA m16n8k16): g_hs1 = fp16(x @ W1) raw ----
#define AST 36
#define SA_W (256 * AST)
#define SBH_W 1280                       // uint32 per B stage (2 ksteps x 32 x 20)
#define GEMM_SMEM ((2 * SA_W + 2 * SBH_W) * 4)   // 83968

__global__ __launch_bounds__(256) void k_gemm1_mma(const float* __restrict__ x) {
    extern __shared__ float sm[];
    float* sA[2] = {sm, sm + SA_W};
    uint32_t* sBu[2] = {(uint32_t*)(sm + 2 * SA_W), (uint32_t*)(sm + 2 * SA_W) + SBH_W};
    int t = threadIdx.x;
    int wid = t >> 5, lane = t & 31;
    int g = lane >> 2, tig = lane & 3;
    int row0 = blockIdx.x * 256 + wid * 32;

    float c[2][8][4];
#pragma unroll
    for (int m = 0; m < 2; m++)
#pragma unroll
        for (int j = 0; j < 8; j++)
#pragma unroll
            for (int q = 0; q < 4; q++) c[m][j][q] = 0.f;

    int arow = t >> 3, ajj = t & 7;
    int argl = blockIdx.x * 256 + arow;

    {
#pragma unroll
        for (int p = 0; p < 8; p++) {
            int row = p * 32 + arow;
            int rg = argl + p * 32; if (rg >= NN) rg = NN - 1;
            cpa16(&sA[0][row * AST + ajj * 4], &x[(size_t)rg * DIN + ajj * 4]);
        }
#pragma unroll
        for (int q = 0; q < 2; q++) {
            int i = q * 256 + t;
            if (i < 320) cpa16(&sBu[0][i * 4], &g_bpkh[i * 4]);
        }
        cpa_commit();
    }

    for (int ch = 0; ch < 16; ch++) {
        int st = ch & 1;
        if (ch < 15) {
            int cn = ch + 1, sn = cn & 1;
#pragma unroll
            for (int p = 0; p < 8; p++) {
                int row = p * 32 + arow;
                int rg = argl + p * 32; if (rg >= NN) rg = NN - 1;
                cpa16(&sA[sn][row * AST + ajj * 4], &x[(size_t)rg * DIN + cn * 32 + ajj * 4]);
            }
#pragma unroll
            for (int q = 0; q < 2; q++) {
                int i = q * 256 + t;
                if (i < 320) cpa16(&sBu[sn][i * 4], &g_bpkh[cn * SBH_W + i * 4]);
            }
            cpa_commit();
            cpa_wait<1>();
        } else {
            cpa_wait<0>();
        }
        __syncthreads();

        const float* A = sA[st];
        const uint32_t* Bh = sBu[st];
#pragma unroll
        for (int ss = 0; ss < 2; ss++) {
            int k0 = ss * 16;
            uint32_t a[2][4];
#pragma unroll
            for (int m = 0; m < 2; m++) {
                int r0 = wid * 32 + m * 16 + g;
                float2 f0 = *(const float2*)&A[r0 * AST + k0 + 2 * tig];
                float2 f1 = *(const float2*)&A[(r0 + 8) * AST + k0 + 2 * tig];
                float2 f2 = *(const float2*)&A[r0 * AST + k0 + 2 * tig + 8];
                float2 f3 = *(const float2*)&A[(r0 + 8) * AST + k0 + 2 * tig + 8];
                a[m][0] = f22h2(f0.x, f0.y);
                a[m][1] = f22h2(f1.x, f1.y);
                a[m][2] = f22h2(f2.x, f2.y);
                a[m][3] = f22h2(f3.x, f3.y);
            }
            const uint4* bp = (const uint4*)&Bh[(ss * 32 + lane) * 20];
            uint4 q0 = bp[0], q1 = bp[1], q2 = bp[2], q3 = bp[3];
            uint32_t b0[8] = {q0.x, q0.y, q0.z, q0.w, q1.x, q1.y, q1.z, q1.w};
            uint32_t b1[8] = {q2.x, q2.y, q2.z, q2.w, q3.x, q3.y, q3.z, q3.w};
#pragma unroll
            for (int j = 0; j < 8; j++) {
#pragma unroll
                for (int m = 0; m < 2; m++) {
                    asm volatile(
                        "mma.sync.aligned.m16n8k16.row.col.f32.f16.f16.f32 "
                        "{%0,%1,%2,%3}, {%4,%5,%6,%7}, {%8,%9}, {%0,%1,%2,%3};"
                        : "+f"(c[m][j][0]), "+f"(c[m][j][1]),
                          "+f"(c[m][j][2]), "+f"(c[m][j][3])
                        : "r"(a[m][0]), "r"(a[m][1]), "r"(a[m][2]), "r"(a[m][3]),
                          "r"(b0[j]), "r"(b1[j]));
                }
            }
        }
        __syncthreads();
    }

    // epilogue: raw fp16 store (dinv applied by k_scale1 after CSR join)
#pragma unroll
    for (int m = 0; m < 2; m++) {
        int rA = row0 + m * 16 + g;
        int rB = rA + 8;
#pragma unroll
        for (int j = 0; j < 8; j++) {
            int col = j * 8 + 2 * tig;
            if (rA < NN) {
                __half2 v = __floats2half2_rn(c[m][j][0], c[m][j][1]);
                *(__half2*)&g_hs1[(size_t)rA * DH + col] = v;
            }
            if (rB < NN) {
                __half2 v = __floats2half2_rn(c[m][j][2], c[m][j][3]);
                *(__half2*)&g_hs1[(size_t)rB * DH + col] = v;
            }
        }
    }
}

// ---------------- scale hs1 by dinv (after CSR join) ----------------
__global__ void k_scale1() {
    int i = blockIdx.x * blockDim.x + threadIdx.x;   // one uint4 = 8 halves
    if (i >= NN * DH / 8) return;
    float di = g_dinv[i >> 3];
    __half2* p = (__half2*)&g_hs1[(size_t)i * 8];
#pragma unroll
    for (int q = 0; q < 4; q++) {
        float2 v = __half22float2(p[q]);
        p[q] = __floats2half2_rn(v.x * di, v.y * di);
    }
}

// ---------------- gather-sum: LDG.128, 4 edges per warp-iteration --------
template <int MODE>
__global__ __launch_bounds__(256) void k_aggsum(const float* __restrict__ bpre) {
    int t = threadIdx.x;
    int lane = t & 31;
    int q = lane >> 3;
    int fl = lane & 7;
    int node = blockIdx.x * 8 + (t >> 5);
    if (node >= NN) return;

    const __half* __restrict__ hin = (MODE == 0) ? g_hs1 : g_hs2;
    int js = g_rowptr[node], je = g_rowptr[node + 1];
    float a0 = 0.f, a1 = 0.f, a2 = 0.f, a3 = 0.f;
    float a4 = 0.f, a5 = 0.f, a6 = 0.f, a7 = 0.f;
    int j = js;
    for (; j + 32 <= je; j += 32) {
        int myc = g_col[j + lane];
#pragma unroll
        for (int l = 0; l < 8; l++) {
            int s = __shfl_sync(0xffffffffu, myc, 4 * l + q);
            uint4 raw = *(const uint4*)&hin[s * DH + fl * 8];
            float2 v0 = __half22float2(*(__half2*)&raw.x);
            float2 v1 = __half22float2(*(__half2*)&raw.y);
            float2 v2 = __half22float2(*(__half2*)&raw.z);
            float2 v3 = __half22float2(*(__half2*)&raw.w);
            a0 += v0.x; a1 += v0.y; a2 += v1.x; a3 += v1.y;
            a4 += v2.x; a5 += v2.y; a6 += v3.x; a7 += v3.y;
        }
    }
    if (j < je) {
        int m = je - j;
        int myc = (j + lane < je) ? g_col[j + lane] : 0;
        int iters = (m + 3) >> 2;
        for (int l = 0; l < iters; l++) {
            int e = 4 * l + q;
            int s = __shfl_sync(0xffffffffu, myc, e);
            if (e < m) {
                uint4 raw = *(const uint4*)&hin[s * DH + fl * 8];
                float2 v0 = __half22float2(*(__half2*)&raw.x);
                float2 v1 = __half22float2(*(__half2*)&raw.y);
                float2 v2 = __half22float2(*(__half2*)&raw.z);
                float2 v3 = __half22float2(*(__half2*)&raw.w);
                a0 += v0.x; a1 += v0.y; a2 += v1.x; a3 += v1.y;
                a4 += v2.x; a5 += v2.y; a6 += v3.x; a7 += v3.y;
            }
        }
    }

#define RED1(v) v += __shfl_down_sync(0xffffffffu, v, 16); \
                v += __shfl_down_sync(0xffffffffu, v, 8);
    RED1(a0) RED1(a1) RED1(a2) RED1(a3) RED1(a4) RED1(a5) RED1(a6) RED1(a7)
#undef RED1

    if (lane < 8) {
        float di = g_dinv[node];
        float4 b0 = *(const float4*)&bpre[fl * 8];
        float4 b1 = *(const float4*)&bpre[fl * 8 + 4];
        a0 = a0 * di + b0.x; a1 = a1 * di + b0.y;
        a2 = a2 * di + b0.z; a3 = a3 * di + b0.w;
        a4 = a4 * di + b1.x; a5 = a5 * di + b1.y;
        a6 = a6 * di + b1.z; a7 = a7 * di + b1.w;
        if (MODE == 0) {
            a0 = fmaxf(a0, 0.f); a1 = fmaxf(a1, 0.f);
            a2 = fmaxf(a2, 0.f); a3 = fmaxf(a3, 0.f);
            a4 = fmaxf(a4, 0.f); a5 = fmaxf(a5, 0.f);
            a6 = fmaxf(a6, 0.f); a7 = fmaxf(a7, 0.f);
        }
        float4 o0 = {a0, a1, a2, a3};
        float4 o1 = {a4, a5, a6, a7};
        *(float4*)&g_a[(size_t)node * DH + fl * 8]     = o0;
        *(float4*)&g_a[(size_t)node * DH + fl * 8 + 4] = o1;
    }
}

// ---------------- mm64 (fp16 MMA): SMEM-staged A ----------------
#define FAST 68
#define MM64_SMEM ((256 * FAST + 4 * 32 * 20) * 4)   // 79872

template <int MODE>
__global__ __launch_bounds__(256) void k_mm64(const float* __restrict__ bpost,
                                              float* __restrict__ out) {
    extern __shared__ float sm2[];
    float* aS = sm2;
    uint32_t* sBu = (uint32_t*)(sm2 + 256 * FAST);   // 4 ksteps x 32 x 20
    int t = threadIdx.x;
    int wid = t >> 5, lane = t & 31;
    int g = lane >> 2, tig = lane & 3;
    int base = blockIdx.x * 256;
    int w32 = wid * 32;

    {
        const float4* src = (const float4*)&g_bpkh[(32 + MODE * 4) * 640];
        float4* dst = (float4*)sBu;
#pragma unroll
        for (int i = 0; i < 3; i++) {
            int idx = t + i * 256;
            if (idx < 640) dst[idx] = src[idx];
        }
    }
#pragma unroll
    for (int i = 0; i < 16; i++) {
        int lr = i * 16 + (t >> 4);
        int rg = base + lr; if (rg >= NN) rg = NN - 1;
        float4 v = *(const float4*)&g_a[(size_t)rg * DH + (t & 15) * 4];
        *(float4*)&aS[lr * FAST + (t & 15) * 4] = v;
    }
    __syncthreads();

    float c[2][8][4];
#pragma unroll
    for (int m = 0; m < 2; m++)
#pragma unroll
        for (int j = 0; j < 8; j++)
#pragma unroll
            for (int q = 0; q < 4; q++) c[m][j][q] = 0.f;

#pragma unroll
    for (int s = 0; s < 4; s++) {
        int k0 = s * 16;
        uint32_t a[2][4];
#pragma unroll
        for (int m = 0; m < 2; m++) {
            int r0 = w32 + m * 16 + g;
            float2 f0 = *(const float2*)&aS[r0 * FAST + k0 + 2 * tig];
            float2 f1 = *(const float2*)&aS[(r0 + 8) * FAST + k0 + 2 * tig];
            float2 f2 = *(const float2*)&aS[r0 * FAST + k0 + 2 * tig + 8];
            float2 f3 = *(const float2*)&aS[(r0 + 8) * FAST + k0 + 2 * tig + 8];
            a[m][0] = f22h2(f0.x, f0.y);
            a[m][1] = f22h2(f1.x, f1.y);
            a[m][2] = f22h2(f2.x, f2.y);
            a[m][3] = f22h2(f3.x, f3.y);
        }
        const uint4* bp = (const uint4*)&sBu[(s * 32 + lane) * 20];
        uint4 q0 = bp[0], q1 = bp[1], q2 = bp[2], q3 = bp[3];
        uint32_t b0[8] = {q0.x, q0.y, q0.z, q0.w, q1.x, q1.y, q1.z, q1.w};
        uint32_t b1[8] = {q2.x, q2.y, q2.z, q2.w, q3.x, q3.y, q3.z, q3.w};
#pragma unroll
        for (int j = 0; j < 8; j++) {
#pragma unroll
            for (int m = 0; m < 2; m++) {
                asm volatile(
                    "mma.sync.aligned.m16n8k16.row.col.f32.f16.f16.f32 "
                    "{%0,%1,%2,%3}, {%4,%5,%6,%7}, {%8,%9}, {%0,%1,%2,%3};"
                    : "+f"(c[m][j][0]), "+f"(c[m][j][1]),
                      "+f"(c[m][j][2]), "+f"(c[m][j][3])
                    : "r"(a[m][0]), "r"(a[m][1]), "r"(a[m][2]), "r"(a[m][3]),
                      "r"(b0[j]), "r"(b1[j]));
            }
        }
    }

    if (MODE == 0) {
#pragma unroll
        for (int m = 0; m < 2; m++) {
            int rA = base + w32 + m * 16 + g, rB = rA + 8;
            float diA = g_dinv[(rA < NN) ? rA : (NN - 1)];
            float diB = g_dinv[(rB < NN) ? rB : (NN - 1)];
#pragma unroll
            for (int j = 0; j < 8; j++) {
                int col = j * 8 + 2 * tig;
                if (rA < NN) {
                    __half2 v = __floats2half2_rn(c[m][j][0] * diA, c[m][j][1] * diA);
                    *(__half2*)&g_hs2[(size_t)rA * DH + col] = v;
                }
                if (rB < NN) {
                    __half2 v = __floats2half2_rn(c[m][j][2] * diB, c[m][j][3] * diB);
                    *(__half2*)&g_hs2[(size_t)rB * DH + col] = v;
                }
            }
        }
    } else {
#pragma unroll
        for (int m = 0; m < 2; m++) {
            int rA = base + w32 + m * 16 + g, rB = rA + 8;
#pragma unroll
            for (int j = 0; j < 8; j++) {
                int col = j * 8 + 2 * tig;
                float2 bq = *(const float2*)&bpost[col];
                if (rA < NN) {
                    float2 v = {c[m][j][0] + bq.x, c[m][j][1] + bq.y};
                    *(float2*)&out[(size_t)rA * DH + col] = v;
                }
                if (rB < NN) {
                    float2 v = {c[m][j][2] + bq.x, c[m][j][3] + bq.y};
                    *(float2*)&out[(size_t)rB * DH + col] = v;
                }
            }
        }
    }
}

// ---------------- launch ----------------
extern "C" void kernel_launch(void* const* d_in, const int* in_sizes, int n_in,
                              void* d_out, int out_size) {
    const float* x    = (const float*)d_in[0];
    const int*   ei   = (const int*)d_in[1];
    const float* W1   = (const float*)d_in[2];
    const float* b1   = (const float*)d_in[3];
    const float* W2   = (const float*)d_in[4];
    const float* b2   = (const float*)d_in[5];
    const float* Wlin = (const float*)d_in[6];
    const float* blin = (const float*)d_in[7];
    float* out = (float*)d_out;

    static cudaStream_t s2 = nullptr;
    static cudaEvent_t e0 = nullptr, e2 = nullptr;
    if (!s2) {   // created on the uncaptured correctness call
        cudaFuncSetAttribute(k_gemm1_mma, cudaFuncAttributeMaxDynamicSharedMemorySize, GEMM_SMEM);
        cudaFuncSetAttribute(k_mm64<0>, cudaFuncAttributeMaxDynamicSharedMemorySize, MM64_SMEM);
        cudaFuncSetAttribute(k_mm64<1>, cudaFuncAttributeMaxDynamicSharedMemorySize, MM64_SMEM);
        cudaStreamCreateWithFlags(&s2, cudaStreamNonBlocking);
        cudaEventCreateWithFlags(&e0, cudaEventDisableTiming);
        cudaEventCreateWithFlags(&e2, cudaEventDisableTiming);
    }

    // fork s2 from capture origin; GEMM has no CSR dependency
    cudaEventRecord(e0, 0);
    cudaStreamWaitEvent(s2, e0, 0);

    k_pack <<<80, 256>>>(W1, W2, Wlin);                        // #0 (main)
    k_init <<<(NN + 255) / 256, 256, 0, s2>>>();               // #1 (s2)
    k_count<<<(ET + 255) / 256, 256, 0, s2>>>(ei);             // #2 (s2)
    k_gemm1_mma<<<(NN + 255) / 256, 256, GEMM_SMEM>>>(x);      // #3 (main) <- ncu
    k_scan1<<<NBLK, 1024, 0, s2>>>();                          // #4 (s2)
    k_scan2<<<1, 128, 0, s2>>>();                              // #5 (s2)
    k_scan3<<<(NN + 255) / 256, 256, 0, s2>>>();               // #6 (s2)
    k_fill <<<(ET + 255) / 256, 256, 0, s2>>>(ei);             // #7 (s2)
    cudaEventRecord(e2, s2);
    cudaStreamWaitEvent(0, e2, 0);                             // join

    k_scale1<<<(NN * DH / 8 + 255) / 256, 256>>>();            // #8
    k_aggsum<0><<<NN / 8 + 1, 256>>>(b1);                      // #9
    k_mm64<0><<<(NN + 255) / 256, 256, MM64_SMEM>>>(nullptr, nullptr);  // #10
    k_aggsum<1><<<NN / 8 + 1, 256>>>(b2);                      // #11
    k_mm64<1><<<(NN + 255) / 256, 256, MM64_SMEM>>>(blin, out);         // #12
}